// round 8
// baseline (speedup 1.0000x reference)
#include <cuda_runtime.h>
#include <cuda_bf16.h>
#include <math.h>
#include <stdint.h>

// ---------------- problem constants ----------------
#define BB   2
#define TT   2048
#define HH   16
#define HKVn 4
#define DD   128
#define GG   4
#define DIMn 2048           // HH*DD
#define KVD  512            // HKVn*DD
#define NTOK (BB*TT)        // 4096
#define HALF 64             // DD/2

// ---------------- device scratch (no allocs allowed) ----------------
__device__ float g_Q[(size_t)NTOK * DIMn];     // 32 MB
__device__ float g_K[(size_t)NTOK * KVD];      // 8 MB
__device__ float g_Y[(size_t)NTOK * DIMn];     // 32 MB
__device__ float g_cos[TT * HALF];
__device__ float g_sin[TT * HALF];
// bf16 hi/lo split operands (16B-aligned for cp.async)
__device__ __align__(16) __nv_bfloat16 g_xh[(size_t)NTOK * DIMn], g_xl[(size_t)NTOK * DIMn];
__device__ __align__(16) __nv_bfloat16 g_wqh[(size_t)DIMn * DIMn], g_wql[(size_t)DIMn * DIMn];
__device__ __align__(16) __nv_bfloat16 g_wkh[(size_t)KVD * DIMn],  g_wkl[(size_t)KVD * DIMn];
__device__ __align__(16) __nv_bfloat16 g_wvh[(size_t)KVD * DIMn],  g_wvl[(size_t)KVD * DIMn];
__device__ __align__(16) __nv_bfloat16 g_wph[(size_t)DIMn * DIMn], g_wpl[(size_t)DIMn * DIMn];
__device__ __align__(16) __nv_bfloat16 g_yh[(size_t)NTOK * DIMn],  g_yl[(size_t)NTOK * DIMn];

// ---------------- PTX helpers (portable, no arch-specific features) -------
__device__ __forceinline__ uint32_t smem_u32(const void* p) {
    uint32_t a;
    asm("{ .reg .u64 t; cvta.to.shared.u64 t, %1; cvt.u32.u64 %0, t; }" : "=r"(a) : "l"(p));
    return a;
}
__device__ __forceinline__ float ex2(float x) {
    float r; asm("ex2.approx.ftz.f32 %0, %1;" : "=f"(r) : "f"(x)); return r;
}
__device__ __forceinline__ void cpa16(uint32_t dst_smem, const void* src_gmem) {
    asm volatile("cp.async.cg.shared.global [%0], [%1], 16;" :: "r"(dst_smem), "l"(src_gmem));
}
#define CP_COMMIT()  asm volatile("cp.async.commit_group;" ::: "memory")
#define CP_WAIT0()   asm volatile("cp.async.wait_group 0;" ::: "memory")
#define CP_WAIT1()   asm volatile("cp.async.wait_group 1;" ::: "memory")

__device__ __forceinline__ void ldsm4(uint32_t* r, uint32_t addr) {
    asm volatile("ldmatrix.sync.aligned.m8n8.x4.shared.b16 {%0,%1,%2,%3}, [%4];"
        : "=r"(r[0]), "=r"(r[1]), "=r"(r[2]), "=r"(r[3]) : "r"(addr));
}
__device__ __forceinline__ void mma16816(float* d, const uint32_t* a, const uint32_t* b) {
    asm volatile("mma.sync.aligned.m16n8k16.row.col.f32.bf16.bf16.f32 "
        "{%0,%1,%2,%3}, {%4,%5,%6,%7}, {%8,%9}, {%0,%1,%2,%3};"
        : "+f"(d[0]), "+f"(d[1]), "+f"(d[2]), "+f"(d[3])
        : "r"(a[0]), "r"(a[1]), "r"(a[2]), "r"(a[3]), "r"(b[0]), "r"(b[1]));
}

#define SW128(off) ((off) ^ (((off) >> 3) & 0x70))

// ---------------- RoPE table (NTK-scaled, T > train_seq_len) --------------
__global__ void rope_table_kernel() {
    int idx = blockIdx.x * blockDim.x + threadIdx.x;
    if (idx >= TT * HALF) return;
    int t = idx >> 6;
    int i = idx & 63;
    double base = 10000.0 * pow(2.0, 128.0 / 126.0);
    double inv  = pow(base, -((double)(2 * i)) / 128.0);
    double ang  = (double)t * inv;
    g_cos[idx] = (float)cos(ang);
    g_sin[idx] = (float)sin(ang);
}

// ---------------- fp32 -> bf16 hi/lo split --------------------------------
__global__ void split_kernel(const float* __restrict__ x,
                             __nv_bfloat16* __restrict__ hi,
                             __nv_bfloat16* __restrict__ lo, int n4) {
    int i = blockIdx.x * blockDim.x + threadIdx.x;
    if (i >= n4) return;
    float4 v = ((const float4*)x)[i];
    __nv_bfloat16 h0 = __float2bfloat16(v.x);
    __nv_bfloat16 h1 = __float2bfloat16(v.y);
    __nv_bfloat16 h2 = __float2bfloat16(v.z);
    __nv_bfloat16 h3 = __float2bfloat16(v.w);
    __nv_bfloat16 l0 = __float2bfloat16(v.x - __bfloat162float(h0));
    __nv_bfloat16 l1 = __float2bfloat16(v.y - __bfloat162float(h1));
    __nv_bfloat16 l2 = __float2bfloat16(v.z - __bfloat162float(h2));
    __nv_bfloat16 l3 = __float2bfloat16(v.w - __bfloat162float(h3));
    ((__nv_bfloat162*)hi)[2 * i]     = __nv_bfloat162(h0, h1);
    ((__nv_bfloat162*)hi)[2 * i + 1] = __nv_bfloat162(h2, h3);
    ((__nv_bfloat162*)lo)[2 * i]     = __nv_bfloat162(l0, l1);
    ((__nv_bfloat162*)lo)[2 * i + 1] = __nv_bfloat162(l2, l3);
}

// ---------------- bf16-split GEMM on mma.sync (HMMA) ----------------------
// C[M,N] = (Ah+Al)[M,K] * (Bh+Bl)[N,K]^T  (3 passes: hh, hl, lh)
// CTA tile 128x128; 8 warps -> warp tile 32x64; BK=64 bf16 (128B SW128 rows);
// cp.async double-buffered stages: 2 x {Ah,Al,Bh,Bl} x 16KB = 128KB smem.
#define GS_ARR    16384
#define GS_STAGE  (4 * GS_ARR)
#define GEMM_SMEM (2 * GS_STAGE)

__device__ __forceinline__ void gemm_fill_stage(
    uint32_t stage, const __nv_bfloat16* const* src, int rowA, int rowB,
    int ck, int K, int tid)
{
#pragma unroll
    for (int it = 0; it < 16; it++) {
        int idx = tid + it * 256;              // 0..4095
        int arr = idx >> 10;                   // 0..3
        int r   = (idx >> 3) & 127;            // row in tile
        int p   = idx & 7;                     // 16B piece in row
        uint32_t off = SW128((uint32_t)(r * 128 + p * 16));
        int grow = ((arr < 2) ? rowA : rowB) + r;
        const __nv_bfloat16* g = src[arr] + (size_t)grow * K + ck * 64 + p * 8;
        cpa16(stage + arr * GS_ARR + off, g);
    }
    CP_COMMIT();
}

__global__ __launch_bounds__(256, 1)
void mma_gemm(const __nv_bfloat16* __restrict__ Ah, const __nv_bfloat16* __restrict__ Al,
              const __nv_bfloat16* __restrict__ Bh, const __nv_bfloat16* __restrict__ Bl,
              float* __restrict__ C, int K, int ldc) {
    extern __shared__ char smc[];
    const uint32_t sb = smem_u32(smc);
    const int tid = threadIdx.x;
    const int wid = tid >> 5;
    const int lane = tid & 31;
    const int wm = wid & 3;          // warp M offset 32*wm
    const int wn = wid >> 2;         // warp N offset 64*wn
    const int rowA = blockIdx.y * 128;
    const int rowB = blockIdx.x * 128;

    const __nv_bfloat16* src[4] = {Ah, Al, Bh, Bl};

    float accf[2][8][4];
#pragma unroll
    for (int mb = 0; mb < 2; mb++)
#pragma unroll
        for (int nb = 0; nb < 8; nb++)
#pragma unroll
            for (int j = 0; j < 4; j++) accf[mb][nb][j] = 0.f;

    const int KT = K >> 6;
    gemm_fill_stage(sb, src, rowA, rowB, 0, K, tid);
    gemm_fill_stage(sb + GS_STAGE, src, rowA, rowB, 1, K, tid);

    // precomputed ldmatrix lane addressing (row, 16B-col within 64-elem row)
    const int aRow = wm * 32 + ((lane >> 3) & 1) * 8 + (lane & 7);   // + mb*16
    const int aCol = (lane >> 4);                                     // + kk*2
    const int bRow = wn * 64 + (lane >> 4) * 8 + (lane & 7);          // + nb4*16
    const int bCol = ((lane >> 3) & 1);                               // + kk*2

    for (int ck = 0; ck < KT; ck++) {
        if (ck + 2 <= KT) CP_WAIT1(); else CP_WAIT0();
        __syncthreads();
        const uint32_t stage = sb + (ck & 1) * GS_STAGE;

        // pass operand offsets: (Ah,Bh), (Ah,Bl), (Al,Bh)
        const uint32_t aoff[3] = {0u, 0u, (uint32_t)GS_ARR};
        const uint32_t boff[3] = {2u * GS_ARR, 3u * GS_ARR, 2u * GS_ARR};
#pragma unroll
        for (int pass = 0; pass < 3; pass++) {
            const uint32_t aBase = stage + aoff[pass];
            const uint32_t bBase = stage + boff[pass];
#pragma unroll
            for (int kk = 0; kk < 4; kk++) {
                uint32_t a[2][4];
#pragma unroll
                for (int mb = 0; mb < 2; mb++) {
                    uint32_t addr = aBase +
                        SW128((uint32_t)((aRow + mb * 16) * 128 + (aCol + kk * 2) * 16));
                    ldsm4(a[mb], addr);
                }
                uint32_t b[4][4];
#pragma unroll
                for (int nb4 = 0; nb4 < 4; nb4++) {
                    uint32_t addr = bBase +
                        SW128((uint32_t)((bRow + nb4 * 16) * 128 + (bCol + kk * 2) * 16));
                    ldsm4(b[nb4], addr);
                }
#pragma unroll
                for (int mb = 0; mb < 2; mb++)
#pragma unroll
                    for (int nb = 0; nb < 8; nb++)
                        mma16816(accf[mb][nb], a[mb], &b[nb >> 1][(nb & 1) * 2]);
            }
        }
        __syncthreads();
        if (ck + 2 < KT)
            gemm_fill_stage(stage, src, rowA, rowB, ck + 2, K, tid);
    }

    // epilogue: direct fp32 stores (float2 per fragment row)
    const int g = lane >> 2;
    const int t2 = (lane & 3) * 2;
#pragma unroll
    for (int mb = 0; mb < 2; mb++) {
        int r0 = rowA + wm * 32 + mb * 16 + g;
#pragma unroll
        for (int nb = 0; nb < 8; nb++) {
            int col = rowB + wn * 64 + nb * 8 + t2;
            float* c0 = C + (size_t)r0 * ldc + col;
            float* c1 = C + (size_t)(r0 + 8) * ldc + col;
            c0[0] = accf[mb][nb][0]; c0[1] = accf[mb][nb][1];
            c1[0] = accf[mb][nb][2]; c1[1] = accf[mb][nb][3];
        }
    }
}

// ---------------- fused RMSNorm + RoPE (+ optional per-head gain) ---------
__global__ void normrope_kernel(float* __restrict__ X, int heads,
                                const float* __restrict__ gain, int use_gain) {
    const int row = blockIdx.x;
    const int h = blockIdx.y;
    const int d = threadIdx.x;
    const int ld = heads * DD;
    float* p = X + (size_t)row * ld + h * DD;

    float v = p[d];
    __shared__ float sh[DD];
    __shared__ float red[4];
    float sq = v * v;
#pragma unroll
    for (int o = 16; o; o >>= 1) sq += __shfl_xor_sync(0xffffffffu, sq, o);
    if ((d & 31) == 0) red[d >> 5] = sq;
    __syncthreads();
    float tot = red[0] + red[1] + red[2] + red[3];
    float r = rsqrtf(tot * (1.0f / DD) + 1.1920929e-7f);
    sh[d] = v * r;
    __syncthreads();
    if (d < HALF) {
        int t = row & (TT - 1);
        float c = g_cos[t * HALF + d];
        float s = g_sin[t * HALF + d];
        float x1 = sh[d], x2 = sh[d + HALF];
        float gg = use_gain ? gain[h] : 1.0f;
        p[d]        = (x1 * c + x2 * s) * gg;
        p[d + HALF] = (-x1 * s + x2 * c) * gg;
    }
}

// ---------------- flash attention (causal, GQA) ---------------------------
// BM=128, BN=64, 512 threads, single-buffered K/V. fp32 SIMT,
// register-resident online softmax in exp2 domain.
#define AT_BM 128
#define AT_BN 64
#define SS_LD 68
#define FL_SMEM ((AT_BM * DD + 2 * AT_BN * DD + AT_BM * SS_LD) * 4)

__global__ __launch_bounds__(512, 1)
void flash_attn_kernel(const float* __restrict__ Q, const float* __restrict__ K,
                       const float* __restrict__ V, float* __restrict__ O) {
    extern __shared__ __align__(16) float smf[];
    float* Qs = smf;                         // 128*128
    float* Ks = Qs + AT_BM * DD;             // 64*128
    float* Vs = Ks + AT_BN * DD;             // 64*128
    float* Ss = Vs + AT_BN * DD;             // 128*68

    const int qb = (gridDim.x - 1) - blockIdx.x;   // large tiles first
    const int bh = blockIdx.y;
    const int b = bh / HH;
    const int h = bh % HH;
    const int kh = h / GG;
    const int q0 = qb * AT_BM;
    const int tid = threadIdx.x;
    const int tx = tid & 15;
    const int ty = tid >> 4;
    const float qscale = 0.08838834764831845f * 1.4426950408889634f;

    const float* Qb = Q + ((size_t)(b * TT + q0)) * DIMn + h * DD;
#pragma unroll
    for (int it = 0; it < 8; it++) {
        int i = tid + it * 512;
        int r = i >> 5, c4 = (i & 31) << 2;
        float4 qv = *(const float4*)(Qb + (size_t)r * DIMn + c4);
        qv.x *= qscale; qv.y *= qscale; qv.z *= qscale; qv.w *= qscale;
        *(float4*)(Qs + r * DD + c4) = qv;
    }

    const float* Kb = K + ((size_t)(b * TT)) * KVD + kh * DD;
    const float* Vb = V + ((size_t)(b * TT)) * KVD + kh * DD;
    const uint32_t KsA = smem_u32(Ks);
    const uint32_t VsA = smem_u32(Vs);

    float m_run[4] = {-INFINITY, -INFINITY, -INFINITY, -INFINITY};
    float l_run[4] = {0.f, 0.f, 0.f, 0.f};
    float acc[4][8];
#pragma unroll
    for (int i = 0; i < 4; i++)
#pragma unroll
        for (int j = 0; j < 8; j++) acc[i][j] = 0.f;

    const int nkb = 2 * qb + 2;
    for (int kb = 0; kb < nkb; kb++) {
        const int k0 = kb * AT_BN;
        __syncthreads();
#pragma unroll
        for (int it = 0; it < 4; it++) {
            int i = tid + it * 512;
            int r = i >> 5, c4 = (i & 31) << 2;
            cpa16(KsA + (r * DD + c4) * 4, Kb + (size_t)(k0 + r) * KVD + c4);
            cpa16(VsA + (r * DD + c4) * 4, Vb + (size_t)(k0 + r) * KVD + c4);
        }
        CP_COMMIT();
        CP_WAIT0();
        __syncthreads();

        float s[4][4];
#pragma unroll
        for (int i = 0; i < 4; i++)
#pragma unroll
            for (int j = 0; j < 4; j++) s[i][j] = 0.f;
        for (int k = 0; k < DD; k += 4) {
            float4 qv[4], kv[4];
#pragma unroll
            for (int i = 0; i < 4; i++) qv[i] = *(const float4*)(Qs + (ty * 4 + i) * DD + k);
#pragma unroll
            for (int j = 0; j < 4; j++) kv[j] = *(const float4*)(Ks + (tx * 4 + j) * DD + k);
#pragma unroll
            for (int i = 0; i < 4; i++)
#pragma unroll
                for (int j = 0; j < 4; j++)
                    s[i][j] += qv[i].x * kv[j].x + qv[i].y * kv[j].y +
                               qv[i].z * kv[j].z + qv[i].w * kv[j].w;
        }
        if (kb >= 2 * qb) {
#pragma unroll
            for (int i = 0; i < 4; i++)
#pragma unroll
                for (int j = 0; j < 4; j++)
                    if ((k0 + tx * 4 + j) > (q0 + ty * 4 + i)) s[i][j] = -INFINITY;
        }

#pragma unroll
        for (int i = 0; i < 4; i++) {
            float mi = fmaxf(fmaxf(s[i][0], s[i][1]), fmaxf(s[i][2], s[i][3]));
            mi = fmaxf(mi, __shfl_xor_sync(0xffffffffu, mi, 1));
            mi = fmaxf(mi, __shfl_xor_sync(0xffffffffu, mi, 2));
            mi = fmaxf(mi, __shfl_xor_sync(0xffffffffu, mi, 4));
            mi = fmaxf(mi, __shfl_xor_sync(0xffffffffu, mi, 8));
            float m_new = fmaxf(m_run[i], mi);
            float alpha = ex2(m_run[i] - m_new);
            m_run[i] = m_new;
            float li = 0.f;
#pragma unroll
            for (int j = 0; j < 4; j++) {
                s[i][j] = ex2(s[i][j] - m_new);
                li += s[i][j];
            }
            li += __shfl_xor_sync(0xffffffffu, li, 1);
            li += __shfl_xor_sync(0xffffffffu, li, 2);
            li += __shfl_xor_sync(0xffffffffu, li, 4);
            li += __shfl_xor_sync(0xffffffffu, li, 8);
            l_run[i] = l_run[i] * alpha + li;
#pragma unroll
            for (int j = 0; j < 8; j++) acc[i][j] *= alpha;
        }

#pragma unroll
        for (int i = 0; i < 4; i++)
#pragma unroll
            for (int j = 0; j < 4; j++)
                Ss[(ty * 4 + i) * SS_LD + tx * 4 + j] = s[i][j];
        __syncthreads();

#pragma unroll 4
        for (int k = 0; k < AT_BN; k++) {
            float4 v0 = *(const float4*)(Vs + k * DD + tx * 8);
            float4 v1 = *(const float4*)(Vs + k * DD + tx * 8 + 4);
            float p0 = Ss[(ty * 4 + 0) * SS_LD + k];
            float p1 = Ss[(ty * 4 + 1) * SS_LD + k];
            float p2 = Ss[(ty * 4 + 2) * SS_LD + k];
            float p3 = Ss[(ty * 4 + 3) * SS_LD + k];
            acc[0][0] += p0 * v0.x; acc[0][1] += p0 * v0.y; acc[0][2] += p0 * v0.z; acc[0][3] += p0 * v0.w;
            acc[0][4] += p0 * v1.x; acc[0][5] += p0 * v1.y; acc[0][6] += p0 * v1.z; acc[0][7] += p0 * v1.w;
            acc[1][0] += p1 * v0.x; acc[1][1] += p1 * v0.y; acc[1][2] += p1 * v0.z; acc[1][3] += p1 * v0.w;
            acc[1][4] += p1 * v1.x; acc[1][5] += p1 * v1.y; acc[1][6] += p1 * v1.z; acc[1][7] += p1 * v1.w;
            acc[2][0] += p2 * v0.x; acc[2][1] += p2 * v0.y; acc[2][2] += p2 * v0.z; acc[2][3] += p2 * v0.w;
            acc[2][4] += p2 * v1.x; acc[2][5] += p2 * v1.y; acc[2][6] += p2 * v1.z; acc[2][7] += p2 * v1.w;
            acc[3][0] += p3 * v0.x; acc[3][1] += p3 * v0.y; acc[3][2] += p3 * v0.z; acc[3][3] += p3 * v0.w;
            acc[3][4] += p3 * v1.x; acc[3][5] += p3 * v1.y; acc[3][6] += p3 * v1.z; acc[3][7] += p3 * v1.w;
        }
    }

    float* Obase = O + ((size_t)(b * TT + q0)) * DIMn + h * DD;
#pragma unroll
    for (int i = 0; i < 4; i++) {
        int r = ty * 4 + i;
        float inv_l = 1.0f / l_run[i];
        float4 o0 = make_float4(acc[i][0] * inv_l, acc[i][1] * inv_l,
                                acc[i][2] * inv_l, acc[i][3] * inv_l);
        float4 o1 = make_float4(acc[i][4] * inv_l, acc[i][5] * inv_l,
                                acc[i][6] * inv_l, acc[i][7] * inv_l);
        *(float4*)(Obase + (size_t)r * DIMn + tx * 8)     = o0;
        *(float4*)(Obase + (size_t)r * DIMn + tx * 8 + 4) = o1;
    }
}

// ---------------- host launcher ----------------
extern "C" void kernel_launch(void* const* d_in, const int* in_sizes, int n_in,
                              void* d_out, int out_size) {
    const float* x     = (const float*)d_in[0];
    const float* Wq    = (const float*)d_in[1];
    const float* Wk    = (const float*)d_in[2];
    const float* Wv    = (const float*)d_in[3];
    const float* Wproj = (const float*)d_in[4];
    const float* qgain = (const float*)d_in[5];
    float* out = (float*)d_out;

    float *q_ptr, *k_ptr, *y_ptr;
    cudaGetSymbolAddress((void**)&q_ptr, g_Q);
    cudaGetSymbolAddress((void**)&k_ptr, g_K);
    cudaGetSymbolAddress((void**)&y_ptr, g_Y);
    __nv_bfloat16 *xh, *xl, *wqh, *wql, *wkh, *wkl, *wvh, *wvl, *wph, *wpl, *yh, *yl;
    cudaGetSymbolAddress((void**)&xh, g_xh);   cudaGetSymbolAddress((void**)&xl, g_xl);
    cudaGetSymbolAddress((void**)&wqh, g_wqh); cudaGetSymbolAddress((void**)&wql, g_wql);
    cudaGetSymbolAddress((void**)&wkh, g_wkh); cudaGetSymbolAddress((void**)&wkl, g_wkl);
    cudaGetSymbolAddress((void**)&wvh, g_wvh); cudaGetSymbolAddress((void**)&wvl, g_wvl);
    cudaGetSymbolAddress((void**)&wph, g_wph); cudaGetSymbolAddress((void**)&wpl, g_wpl);
    cudaGetSymbolAddress((void**)&yh, g_yh);   cudaGetSymbolAddress((void**)&yl, g_yl);

    float* v_out = out + (size_t)NTOK * DIMn;   // v is the second output

    cudaFuncSetAttribute(mma_gemm, cudaFuncAttributeMaxDynamicSharedMemorySize, GEMM_SMEM);
    cudaFuncSetAttribute(flash_attn_kernel, cudaFuncAttributeMaxDynamicSharedMemorySize, FL_SMEM);

    // 1. RoPE tables + operand splits
    rope_table_kernel<<<(TT * HALF + 255) / 256, 256>>>();
    split_kernel<<<(NTOK * DIMn / 4 + 255) / 256, 256>>>(x, xh, xl, NTOK * DIMn / 4);
    split_kernel<<<(DIMn * DIMn / 4 + 255) / 256, 256>>>(Wq, wqh, wql, DIMn * DIMn / 4);
    split_kernel<<<(KVD * DIMn / 4 + 255) / 256, 256>>>(Wk, wkh, wkl, KVD * DIMn / 4);
    split_kernel<<<(KVD * DIMn / 4 + 255) / 256, 256>>>(Wv, wvh, wvl, KVD * DIMn / 4);
    split_kernel<<<(DIMn * DIMn / 4 + 255) / 256, 256>>>(Wproj, wph, wpl, DIMn * DIMn / 4);

    // 2. QKV projections on HMMA (V written directly into output tail)
    mma_gemm<<<dim3(DIMn / 128, NTOK / 128), 256, GEMM_SMEM>>>(xh, xl, wqh, wql, q_ptr, DIMn, DIMn);
    mma_gemm<<<dim3(KVD / 128, NTOK / 128), 256, GEMM_SMEM>>>(xh, xl, wkh, wkl, k_ptr, DIMn, KVD);
    mma_gemm<<<dim3(KVD / 128, NTOK / 128), 256, GEMM_SMEM>>>(xh, xl, wvh, wvl, v_out, DIMn, KVD);

    // 3. RMSNorm + RoPE (+ q gain)
    normrope_kernel<<<dim3(NTOK, HH), 128>>>(q_ptr, HH, qgain, 1);
    normrope_kernel<<<dim3(NTOK, HKVn), 128>>>(k_ptr, HKVn, nullptr, 0);

    // 4. causal GQA flash attention
    flash_attn_kernel<<<dim3(TT / AT_BM, BB * HH), 512, FL_SMEM>>>(q_ptr, k_ptr, v_out, y_ptr);

    // 5. output projection on HMMA
    split_kernel<<<(NTOK * DIMn / 4 + 255) / 256, 256>>>(y_ptr, yh, yl, NTOK * DIMn / 4);
    mma_gemm<<<dim3(DIMn / 128, NTOK / 128), 256, GEMM_SMEM>>>(yh, yl, wph, wpl, out, DIMn, DIMn);
}

// round 9
// speedup vs baseline: 2.2157x; 2.2157x over previous
#include <cuda_runtime.h>
#include <cuda_bf16.h>
#include <math.h>
#include <stdint.h>

// ---------------- problem constants ----------------
#define BB   2
#define TT   2048
#define HH   16
#define HKVn 4
#define DD   128
#define GG   4
#define DIMn 2048           // HH*DD
#define KVD  512            // HKVn*DD
#define NTOK (BB*TT)        // 4096
#define HALF 64             // DD/2

// ---------------- device scratch (no allocs allowed) ----------------
__device__ float g_Q[(size_t)NTOK * DIMn];     // 32 MB
__device__ float g_K[(size_t)NTOK * KVD];      // 8 MB
__device__ float g_Y[(size_t)NTOK * DIMn];     // 32 MB
__device__ float g_cos[TT * HALF];
__device__ float g_sin[TT * HALF];
// bf16 hi/lo split operands (16B-aligned for cp.async)
__device__ __align__(16) __nv_bfloat16 g_xh[(size_t)NTOK * DIMn], g_xl[(size_t)NTOK * DIMn];
__device__ __align__(16) __nv_bfloat16 g_wqh[(size_t)DIMn * DIMn], g_wql[(size_t)DIMn * DIMn];
__device__ __align__(16) __nv_bfloat16 g_wkh[(size_t)KVD * DIMn],  g_wkl[(size_t)KVD * DIMn];
__device__ __align__(16) __nv_bfloat16 g_wvh[(size_t)KVD * DIMn],  g_wvl[(size_t)KVD * DIMn];
__device__ __align__(16) __nv_bfloat16 g_wph[(size_t)DIMn * DIMn], g_wpl[(size_t)DIMn * DIMn];
__device__ __align__(16) __nv_bfloat16 g_yh[(size_t)NTOK * DIMn],  g_yl[(size_t)NTOK * DIMn];

// ---------------- PTX helpers (portable, no arch-specific features) -------
__device__ __forceinline__ uint32_t smem_u32(const void* p) {
    uint32_t a;
    asm("{ .reg .u64 t; cvta.to.shared.u64 t, %1; cvt.u32.u64 %0, t; }" : "=r"(a) : "l"(p));
    return a;
}
__device__ __forceinline__ float ex2(float x) {
    float r; asm("ex2.approx.ftz.f32 %0, %1;" : "=f"(r) : "f"(x)); return r;
}
__device__ __forceinline__ void cpa16(uint32_t dst_smem, const void* src_gmem) {
    asm volatile("cp.async.cg.shared.global [%0], [%1], 16;" :: "r"(dst_smem), "l"(src_gmem));
}
#define CP_COMMIT()  asm volatile("cp.async.commit_group;" ::: "memory")
#define CP_WAIT0()   asm volatile("cp.async.wait_group 0;" ::: "memory")
#define CP_WAIT1()   asm volatile("cp.async.wait_group 1;" ::: "memory")

__device__ __forceinline__ void ldsm4(uint32_t* r, uint32_t addr) {
    asm volatile("ldmatrix.sync.aligned.m8n8.x4.shared.b16 {%0,%1,%2,%3}, [%4];"
        : "=r"(r[0]), "=r"(r[1]), "=r"(r[2]), "=r"(r[3]) : "r"(addr));
}
__device__ __forceinline__ void mma16816(float* d, const uint32_t* a, const uint32_t* b) {
    asm volatile("mma.sync.aligned.m16n8k16.row.col.f32.bf16.bf16.f32 "
        "{%0,%1,%2,%3}, {%4,%5,%6,%7}, {%8,%9}, {%0,%1,%2,%3};"
        : "+f"(d[0]), "+f"(d[1]), "+f"(d[2]), "+f"(d[3])
        : "r"(a[0]), "r"(a[1]), "r"(a[2]), "r"(a[3]), "r"(b[0]), "r"(b[1]));
}

#define SW128(off) ((off) ^ (((off) >> 3) & 0x70))

// ---------------- RoPE table (NTK-scaled, T > train_seq_len) --------------
__global__ void rope_table_kernel() {
    int idx = blockIdx.x * blockDim.x + threadIdx.x;
    if (idx >= TT * HALF) return;
    int t = idx >> 6;
    int i = idx & 63;
    double base = 10000.0 * pow(2.0, 128.0 / 126.0);
    double inv  = pow(base, -((double)(2 * i)) / 128.0);
    double ang  = (double)t * inv;
    g_cos[idx] = (float)cos(ang);
    g_sin[idx] = (float)sin(ang);
}

// ---------------- fp32 -> bf16 hi/lo split --------------------------------
__global__ void split_kernel(const float* __restrict__ x,
                             __nv_bfloat16* __restrict__ hi,
                             __nv_bfloat16* __restrict__ lo, int n4) {
    int i = blockIdx.x * blockDim.x + threadIdx.x;
    if (i >= n4) return;
    float4 v = ((const float4*)x)[i];
    __nv_bfloat16 h0 = __float2bfloat16(v.x);
    __nv_bfloat16 h1 = __float2bfloat16(v.y);
    __nv_bfloat16 h2 = __float2bfloat16(v.z);
    __nv_bfloat16 h3 = __float2bfloat16(v.w);
    __nv_bfloat16 l0 = __float2bfloat16(v.x - __bfloat162float(h0));
    __nv_bfloat16 l1 = __float2bfloat16(v.y - __bfloat162float(h1));
    __nv_bfloat16 l2 = __float2bfloat16(v.z - __bfloat162float(h2));
    __nv_bfloat16 l3 = __float2bfloat16(v.w - __bfloat162float(h3));
    ((__nv_bfloat162*)hi)[2 * i]     = __nv_bfloat162(h0, h1);
    ((__nv_bfloat162*)hi)[2 * i + 1] = __nv_bfloat162(h2, h3);
    ((__nv_bfloat162*)lo)[2 * i]     = __nv_bfloat162(l0, l1);
    ((__nv_bfloat162*)lo)[2 * i + 1] = __nv_bfloat162(l2, l3);
}

// ---------------- bf16-split GEMM on mma.sync (HMMA) ----------------------
// C[M,N] = (Ah+Al)[M,K] * (Bh+Bl)[N,K]^T  (3 passes: hh, hl, lh)
// CTA tile 128x128; 8 warps -> warp tile 32x64; BK=64 bf16 (128B SW128 rows);
// cp.async double-buffered stages: 2 x {Ah,Al,Bh,Bl} x 16KB = 128KB smem.
#define GS_ARR    16384
#define GS_STAGE  (4 * GS_ARR)
#define GEMM_SMEM (2 * GS_STAGE)

__device__ __forceinline__ void gemm_fill_stage(
    uint32_t stage, const __nv_bfloat16* const* src, int rowA, int rowB,
    int ck, int K, int tid)
{
#pragma unroll
    for (int it = 0; it < 16; it++) {
        int idx = tid + it * 256;              // 0..4095
        int arr = idx >> 10;                   // 0..3
        int r   = (idx >> 3) & 127;            // row in tile
        int p   = idx & 7;                     // 16B piece in row
        uint32_t off = SW128((uint32_t)(r * 128 + p * 16));
        int grow = ((arr < 2) ? rowA : rowB) + r;
        const __nv_bfloat16* g = src[arr] + (size_t)grow * K + ck * 64 + p * 8;
        cpa16(stage + arr * GS_ARR + off, g);
    }
    CP_COMMIT();
}

__device__ __forceinline__ void mma_gemm_body(
    const __nv_bfloat16* __restrict__ Ah, const __nv_bfloat16* __restrict__ Al,
    const __nv_bfloat16* __restrict__ Bh, const __nv_bfloat16* __restrict__ Bl,
    float* __restrict__ C, int K, int ldc, int rowA, int rowB, uint32_t sb)
{
    const int tid = threadIdx.x;
    const int wid = tid >> 5;
    const int lane = tid & 31;
    const int wm = wid & 3;          // warp M offset 32*wm
    const int wn = wid >> 2;         // warp N offset 64*wn

    const __nv_bfloat16* src[4] = {Ah, Al, Bh, Bl};

    float accf[2][8][4];
#pragma unroll
    for (int mb = 0; mb < 2; mb++)
#pragma unroll
        for (int nb = 0; nb < 8; nb++)
#pragma unroll
            for (int j = 0; j < 4; j++) accf[mb][nb][j] = 0.f;

    const int KT = K >> 6;
    gemm_fill_stage(sb, src, rowA, rowB, 0, K, tid);
    gemm_fill_stage(sb + GS_STAGE, src, rowA, rowB, 1, K, tid);

    const int aRow = wm * 32 + ((lane >> 3) & 1) * 8 + (lane & 7);   // + mb*16
    const int aCol = (lane >> 4);                                     // + kk*2
    const int bRow = wn * 64 + (lane >> 4) * 8 + (lane & 7);          // + nb4*16
    const int bCol = ((lane >> 3) & 1);                               // + kk*2

    for (int ck = 0; ck < KT; ck++) {
        if (ck + 2 <= KT) CP_WAIT1(); else CP_WAIT0();
        __syncthreads();
        const uint32_t stage = sb + (ck & 1) * GS_STAGE;

        const uint32_t aoff[3] = {0u, 0u, (uint32_t)GS_ARR};
        const uint32_t boff[3] = {2u * GS_ARR, 3u * GS_ARR, 2u * GS_ARR};
#pragma unroll
        for (int pass = 0; pass < 3; pass++) {
            const uint32_t aBase = stage + aoff[pass];
            const uint32_t bBase = stage + boff[pass];
#pragma unroll
            for (int kk = 0; kk < 4; kk++) {
                uint32_t a[2][4];
#pragma unroll
                for (int mb = 0; mb < 2; mb++) {
                    uint32_t addr = aBase +
                        SW128((uint32_t)((aRow + mb * 16) * 128 + (aCol + kk * 2) * 16));
                    ldsm4(a[mb], addr);
                }
                uint32_t b[4][4];
#pragma unroll
                for (int nb4 = 0; nb4 < 4; nb4++) {
                    uint32_t addr = bBase +
                        SW128((uint32_t)((bRow + nb4 * 16) * 128 + (bCol + kk * 2) * 16));
                    ldsm4(b[nb4], addr);
                }
#pragma unroll
                for (int mb = 0; mb < 2; mb++)
#pragma unroll
                    for (int nb = 0; nb < 8; nb++)
                        mma16816(accf[mb][nb], a[mb], &b[nb >> 1][(nb & 1) * 2]);
            }
        }
        __syncthreads();
        if (ck + 2 < KT)
            gemm_fill_stage(stage, src, rowA, rowB, ck + 2, K, tid);
    }

    const int g = lane >> 2;
    const int t2 = (lane & 3) * 2;
#pragma unroll
    for (int mb = 0; mb < 2; mb++) {
        int r0 = rowA + wm * 32 + mb * 16 + g;
#pragma unroll
        for (int nb = 0; nb < 8; nb++) {
            int col = rowB + wn * 64 + nb * 8 + t2;
            float* c0 = C + (size_t)r0 * ldc + col;
            float* c1 = C + (size_t)(r0 + 8) * ldc + col;
            c0[0] = accf[mb][nb][0]; c0[1] = accf[mb][nb][1];
            c1[0] = accf[mb][nb][2]; c1[1] = accf[mb][nb][3];
        }
    }
}

__global__ __launch_bounds__(256, 1)
void mma_gemm(const __nv_bfloat16* __restrict__ Ah, const __nv_bfloat16* __restrict__ Al,
              const __nv_bfloat16* __restrict__ Bh, const __nv_bfloat16* __restrict__ Bl,
              float* __restrict__ C, int K, int ldc) {
    extern __shared__ char smc[];
    mma_gemm_body(Ah, Al, Bh, Bl, C, K, ldc,
                  blockIdx.y * 128, blockIdx.x * 128, smem_u32(smc));
}

// fused K/V projection: grid.x = 8 (4 K col-blocks then 4 V col-blocks)
__global__ __launch_bounds__(256, 1)
void mma_gemm_kv(const __nv_bfloat16* __restrict__ xh, const __nv_bfloat16* __restrict__ xl,
                 const __nv_bfloat16* __restrict__ wkh, const __nv_bfloat16* __restrict__ wkl,
                 const __nv_bfloat16* __restrict__ wvh, const __nv_bfloat16* __restrict__ wvl,
                 float* __restrict__ Ck, float* __restrict__ Cv) {
    extern __shared__ char smc[];
    int nb = blockIdx.x;
    const __nv_bfloat16 *bh, *bl;
    float* C;
    if (nb < 4) { bh = wkh; bl = wkl; C = Ck; }
    else        { bh = wvh; bl = wvl; C = Cv; nb -= 4; }
    mma_gemm_body(xh, xl, bh, bl, C, DIMn, KVD,
                  blockIdx.y * 128, nb * 128, smem_u32(smc));
}

// ---------------- fused RMSNorm + RoPE (+ optional per-head gain) ---------
__global__ void normrope_kernel(float* __restrict__ X, int heads,
                                const float* __restrict__ gain, int use_gain) {
    const int row = blockIdx.x;
    const int h = blockIdx.y;
    const int d = threadIdx.x;
    const int ld = heads * DD;
    float* p = X + (size_t)row * ld + h * DD;

    float v = p[d];
    __shared__ float sh[DD];
    __shared__ float red[4];
    float sq = v * v;
#pragma unroll
    for (int o = 16; o; o >>= 1) sq += __shfl_xor_sync(0xffffffffu, sq, o);
    if ((d & 31) == 0) red[d >> 5] = sq;
    __syncthreads();
    float tot = red[0] + red[1] + red[2] + red[3];
    float r = rsqrtf(tot * (1.0f / DD) + 1.1920929e-7f);
    sh[d] = v * r;
    __syncthreads();
    if (d < HALF) {
        int t = row & (TT - 1);
        float c = g_cos[t * HALF + d];
        float s = g_sin[t * HALF + d];
        float x1 = sh[d], x2 = sh[d + HALF];
        float gg = use_gain ? gain[h] : 1.0f;
        p[d]        = (x1 * c + x2 * s) * gg;
        p[d + HALF] = (-x1 * s + x2 * c) * gg;
    }
}

// ---------------- flash attention (causal, GQA) ---------------------------
// BM=BN=64, 256 threads, cp.async double-buffered K/V, register online softmax.
// Ks stored with per-row piece swizzle (p ^= (r>>2)&7) -> conflict-free kv loads.
// PV columns remapped to {tx*4, 64+tx*4} -> conflict-free V loads.
#define AT_BM 64
#define AT_BN 64
#define SS_LD 68
#define FL_SMEM ((64 * 128 * 5 + 64 * SS_LD) * 4)

__global__ __launch_bounds__(256, 1)
void flash_attn_kernel(const float* __restrict__ Q, const float* __restrict__ K,
                       const float* __restrict__ V, float* __restrict__ O) {
    extern __shared__ __align__(16) float smf[];
    float* Qs  = smf;                 // 64*128
    float* Ks0 = smf + 8192;
    float* Ks1 = smf + 16384;
    float* Vs0 = smf + 24576;
    float* Vs1 = smf + 32768;
    float* Ss  = smf + 40960;         // 64*68

    const int qb = (gridDim.x - 1) - blockIdx.x;   // big tiles first
    const int bh = blockIdx.y;
    const int b = bh / HH;
    const int h = bh % HH;
    const int kh = h / GG;
    const int q0 = qb * AT_BM;
    const int tid = threadIdx.x;
    const int tx = tid & 15;
    const int ty = tid >> 4;
    const float qscale = 0.08838834764831845f * 1.4426950408889634f;  // /sqrt(D)*log2(e)

    // load Q tile (pre-scaled)
    const float* Qb = Q + ((size_t)(b * TT + q0)) * DIMn + h * DD;
    for (int i = tid; i < AT_BM * DD / 4; i += 256) {
        int r = i >> 5, c4 = (i & 31) << 2;
        float4 qv = *(const float4*)(Qb + (size_t)r * DIMn + c4);
        qv.x *= qscale; qv.y *= qscale; qv.z *= qscale; qv.w *= qscale;
        *(float4*)(Qs + r * DD + c4) = qv;
    }

    const float* Kb = K + ((size_t)(b * TT)) * KVD + kh * DD;
    const float* Vb = V + ((size_t)(b * TT)) * KVD + kh * DD;
    const uint32_t Ks0A = smem_u32(Ks0), Ks1A = smem_u32(Ks1);
    const uint32_t Vs0A = smem_u32(Vs0), Vs1A = smem_u32(Vs1);

    // prologue: async-load K/V block 0 into buffer 0 (K piece-swizzled)
    for (int i = tid; i < AT_BN * DD / 4; i += 256) {
        int r = i >> 5, p = i & 31;
        int psw = p ^ ((r >> 2) & 7);
        cpa16(Ks0A + r * 512 + psw * 16, Kb + (size_t)r * KVD + p * 4);
        cpa16(Vs0A + r * 512 + p * 16,   Vb + (size_t)r * KVD + p * 4);
    }
    CP_COMMIT();

    float m_run[4] = {-INFINITY, -INFINITY, -INFINITY, -INFINITY};
    float l_run[4] = {0.f, 0.f, 0.f, 0.f};
    float acc[4][8];
#pragma unroll
    for (int i = 0; i < 4; i++)
#pragma unroll
        for (int j = 0; j < 8; j++) acc[i][j] = 0.f;

    const int nkb = qb + 1;
    for (int kb = 0; kb < nkb; kb++) {
        const int cur = kb & 1;
        const float* Ksc = cur ? Ks1 : Ks0;
        const float* Vsc = cur ? Vs1 : Vs0;
        const uint32_t KsnA = cur ? Ks0A : Ks1A;
        const uint32_t VsnA = cur ? Vs0A : Vs1A;

        __syncthreads();   // prior iter done reading next buffer + Ss
        if (kb + 1 < nkb) {
            const float* Kn = Kb + (size_t)(kb + 1) * AT_BN * KVD;
            const float* Vn = Vb + (size_t)(kb + 1) * AT_BN * KVD;
            for (int i = tid; i < AT_BN * DD / 4; i += 256) {
                int r = i >> 5, p = i & 31;
                int psw = p ^ ((r >> 2) & 7);
                cpa16(KsnA + r * 512 + psw * 16, Kn + (size_t)r * KVD + p * 4);
                cpa16(VsnA + r * 512 + p * 16,   Vn + (size_t)r * KVD + p * 4);
            }
            CP_COMMIT();
            CP_WAIT1();
        } else {
            CP_WAIT0();
        }
        __syncthreads();   // current buffer visible to all

        // S = Qs * Ks^T  (each thread 4x4); Ks piece-swizzled by tx
        float s[4][4];
#pragma unroll
        for (int i = 0; i < 4; i++)
#pragma unroll
            for (int j = 0; j < 4; j++) s[i][j] = 0.f;
        const int ksw = (tx & 7);
        for (int k = 0; k < DD; k += 4) {
            int kcol = (((k >> 2) ^ ksw) << 2);
            float4 qv[4], kv[4];
#pragma unroll
            for (int i = 0; i < 4; i++) qv[i] = *(const float4*)(Qs + (ty * 4 + i) * DD + k);
#pragma unroll
            for (int j = 0; j < 4; j++) kv[j] = *(const float4*)(Ksc + (tx * 4 + j) * DD + kcol);
#pragma unroll
            for (int i = 0; i < 4; i++)
#pragma unroll
                for (int j = 0; j < 4; j++)
                    s[i][j] += qv[i].x * kv[j].x + qv[i].y * kv[j].y +
                               qv[i].z * kv[j].z + qv[i].w * kv[j].w;
        }
        if (kb == qb) {   // diagonal block: causal mask
#pragma unroll
            for (int i = 0; i < 4; i++)
#pragma unroll
                for (int j = 0; j < 4; j++)
                    if ((tx * 4 + j) > (ty * 4 + i)) s[i][j] = -INFINITY;
        }

        // register online softmax: 16 lanes share each row
#pragma unroll
        for (int i = 0; i < 4; i++) {
            float mi = fmaxf(fmaxf(s[i][0], s[i][1]), fmaxf(s[i][2], s[i][3]));
            mi = fmaxf(mi, __shfl_xor_sync(0xffffffffu, mi, 1));
            mi = fmaxf(mi, __shfl_xor_sync(0xffffffffu, mi, 2));
            mi = fmaxf(mi, __shfl_xor_sync(0xffffffffu, mi, 4));
            mi = fmaxf(mi, __shfl_xor_sync(0xffffffffu, mi, 8));
            float m_new = fmaxf(m_run[i], mi);
            float alpha = ex2(m_run[i] - m_new);
            m_run[i] = m_new;
            float li = 0.f;
#pragma unroll
            for (int j = 0; j < 4; j++) {
                s[i][j] = ex2(s[i][j] - m_new);
                li += s[i][j];
            }
            li += __shfl_xor_sync(0xffffffffu, li, 1);
            li += __shfl_xor_sync(0xffffffffu, li, 2);
            li += __shfl_xor_sync(0xffffffffu, li, 4);
            li += __shfl_xor_sync(0xffffffffu, li, 8);
            l_run[i] = l_run[i] * alpha + li;
#pragma unroll
            for (int j = 0; j < 8; j++) acc[i][j] *= alpha;
        }

        // publish P
#pragma unroll
        for (int i = 0; i < 4; i++)
#pragma unroll
            for (int j = 0; j < 4; j++)
                Ss[(ty * 4 + i) * SS_LD + tx * 4 + j] = s[i][j];
        __syncthreads();

        // O += P @ V   (cols {tx*4..+3} and {64+tx*4..+3} -> conflict-free V reads)
#pragma unroll 4
        for (int k = 0; k < AT_BN; k++) {
            float4 v0 = *(const float4*)(Vsc + k * DD + tx * 4);
            float4 v1 = *(const float4*)(Vsc + k * DD + 64 + tx * 4);
            float p0 = Ss[(ty * 4 + 0) * SS_LD + k];
            float p1 = Ss[(ty * 4 + 1) * SS_LD + k];
            float p2 = Ss[(ty * 4 + 2) * SS_LD + k];
            float p3 = Ss[(ty * 4 + 3) * SS_LD + k];
            acc[0][0] += p0 * v0.x; acc[0][1] += p0 * v0.y; acc[0][2] += p0 * v0.z; acc[0][3] += p0 * v0.w;
            acc[0][4] += p0 * v1.x; acc[0][5] += p0 * v1.y; acc[0][6] += p0 * v1.z; acc[0][7] += p0 * v1.w;
            acc[1][0] += p1 * v0.x; acc[1][1] += p1 * v0.y; acc[1][2] += p1 * v0.z; acc[1][3] += p1 * v0.w;
            acc[1][4] += p1 * v1.x; acc[1][5] += p1 * v1.y; acc[1][6] += p1 * v1.z; acc[1][7] += p1 * v1.w;
            acc[2][0] += p2 * v0.x; acc[2][1] += p2 * v0.y; acc[2][2] += p2 * v0.z; acc[2][3] += p2 * v0.w;
            acc[2][4] += p2 * v1.x; acc[2][5] += p2 * v1.y; acc[2][6] += p2 * v1.z; acc[2][7] += p2 * v1.w;
            acc[3][0] += p3 * v0.x; acc[3][1] += p3 * v0.y; acc[3][2] += p3 * v0.z; acc[3][3] += p3 * v0.w;
            acc[3][4] += p3 * v1.x; acc[3][5] += p3 * v1.y; acc[3][6] += p3 * v1.z; acc[3][7] += p3 * v1.w;
        }
    }

    // epilogue: divide by l, write out (cols tx*4 and 64+tx*4)
    float* Obase = O + ((size_t)(b * TT + q0)) * DIMn + h * DD;
#pragma unroll
    for (int i = 0; i < 4; i++) {
        int r = ty * 4 + i;
        float inv_l = 1.0f / l_run[i];
        float4 o0 = make_float4(acc[i][0] * inv_l, acc[i][1] * inv_l,
                                acc[i][2] * inv_l, acc[i][3] * inv_l);
        float4 o1 = make_float4(acc[i][4] * inv_l, acc[i][5] * inv_l,
                                acc[i][6] * inv_l, acc[i][7] * inv_l);
        *(float4*)(Obase + (size_t)r * DIMn + tx * 4)      = o0;
        *(float4*)(Obase + (size_t)r * DIMn + 64 + tx * 4) = o1;
    }
}

// ---------------- host launcher ----------------
extern "C" void kernel_launch(void* const* d_in, const int* in_sizes, int n_in,
                              void* d_out, int out_size) {
    const float* x     = (const float*)d_in[0];
    const float* Wq    = (const float*)d_in[1];
    const float* Wk    = (const float*)d_in[2];
    const float* Wv    = (const float*)d_in[3];
    const float* Wproj = (const float*)d_in[4];
    const float* qgain = (const float*)d_in[5];
    float* out = (float*)d_out;

    float *q_ptr, *k_ptr, *y_ptr;
    cudaGetSymbolAddress((void**)&q_ptr, g_Q);
    cudaGetSymbolAddress((void**)&k_ptr, g_K);
    cudaGetSymbolAddress((void**)&y_ptr, g_Y);
    __nv_bfloat16 *xh, *xl, *wqh, *wql, *wkh, *wkl, *wvh, *wvl, *wph, *wpl, *yh, *yl;
    cudaGetSymbolAddress((void**)&xh, g_xh);   cudaGetSymbolAddress((void**)&xl, g_xl);
    cudaGetSymbolAddress((void**)&wqh, g_wqh); cudaGetSymbolAddress((void**)&wql, g_wql);
    cudaGetSymbolAddress((void**)&wkh, g_wkh); cudaGetSymbolAddress((void**)&wkl, g_wkl);
    cudaGetSymbolAddress((void**)&wvh, g_wvh); cudaGetSymbolAddress((void**)&wvl, g_wvl);
    cudaGetSymbolAddress((void**)&wph, g_wph); cudaGetSymbolAddress((void**)&wpl, g_wpl);
    cudaGetSymbolAddress((void**)&yh, g_yh);   cudaGetSymbolAddress((void**)&yl, g_yl);

    float* v_out = out + (size_t)NTOK * DIMn;   // v is the second output

    cudaFuncSetAttribute(mma_gemm, cudaFuncAttributeMaxDynamicSharedMemorySize, GEMM_SMEM);
    cudaFuncSetAttribute(mma_gemm_kv, cudaFuncAttributeMaxDynamicSharedMemorySize, GEMM_SMEM);
    cudaFuncSetAttribute(flash_attn_kernel, cudaFuncAttributeMaxDynamicSharedMemorySize, FL_SMEM);

    // 1. RoPE tables + operand splits
    rope_table_kernel<<<(TT * HALF + 255) / 256, 256>>>();
    split_kernel<<<(NTOK * DIMn / 4 + 255) / 256, 256>>>(x, xh, xl, NTOK * DIMn / 4);
    split_kernel<<<(DIMn * DIMn / 4 + 255) / 256, 256>>>(Wq, wqh, wql, DIMn * DIMn / 4);
    split_kernel<<<(KVD * DIMn / 4 + 255) / 256, 256>>>(Wk, wkh, wkl, KVD * DIMn / 4);
    split_kernel<<<(KVD * DIMn / 4 + 255) / 256, 256>>>(Wv, wvh, wvl, KVD * DIMn / 4);
    split_kernel<<<(DIMn * DIMn / 4 + 255) / 256, 256>>>(Wproj, wph, wpl, DIMn * DIMn / 4);

    // 2. QKV projections on HMMA (V written directly into output tail; K/V fused)
    mma_gemm<<<dim3(DIMn / 128, NTOK / 128), 256, GEMM_SMEM>>>(xh, xl, wqh, wql, q_ptr, DIMn, DIMn);
    mma_gemm_kv<<<dim3(8, NTOK / 128), 256, GEMM_SMEM>>>(xh, xl, wkh, wkl, wvh, wvl, k_ptr, v_out);

    // 3. RMSNorm + RoPE (+ q gain)
    normrope_kernel<<<dim3(NTOK, HH), 128>>>(q_ptr, HH, qgain, 1);
    normrope_kernel<<<dim3(NTOK, HKVn), 128>>>(k_ptr, HKVn, nullptr, 0);

    // 4. causal GQA flash attention
    flash_attn_kernel<<<dim3(TT / AT_BM, BB * HH), 256, FL_SMEM>>>(q_ptr, k_ptr, v_out, y_ptr);

    // 5. output projection on HMMA
    split_kernel<<<(NTOK * DIMn / 4 + 255) / 256, 256>>>(y_ptr, yh, yl, NTOK * DIMn / 4);
    mma_gemm<<<dim3(DIMn / 128, NTOK / 128), 256, GEMM_SMEM>>>(yh, yl, wph, wpl, out, DIMn, DIMn);
}

// round 10
// speedup vs baseline: 5.2636x; 2.3756x over previous
#include <cuda_runtime.h>
#include <cuda_bf16.h>
#include <math.h>
#include <stdint.h>

// ---------------- problem constants ----------------
#define BB   2
#define TT   2048
#define HH   16
#define HKVn 4
#define DD   128
#define GG   4
#define DIMn 2048           // HH*DD
#define KVD  512            // HKVn*DD
#define NTOK (BB*TT)        // 4096
#define HALF 64             // DD/2

// ---------------- device scratch (no allocs allowed) ----------------
__device__ float g_Q[(size_t)NTOK * DIMn];     // 32 MB
__device__ float g_K[(size_t)NTOK * KVD];      // 8 MB
__device__ float g_Y[(size_t)NTOK * DIMn];     // 32 MB
__device__ float g_cos[TT * HALF];
__device__ float g_sin[TT * HALF];
// bf16 hi/lo split operands (16B-aligned for cp.async)
__device__ __align__(16) __nv_bfloat16 g_xh[(size_t)NTOK * DIMn], g_xl[(size_t)NTOK * DIMn];
__device__ __align__(16) __nv_bfloat16 g_wqh[(size_t)DIMn * DIMn], g_wql[(size_t)DIMn * DIMn];
__device__ __align__(16) __nv_bfloat16 g_wkh[(size_t)KVD * DIMn],  g_wkl[(size_t)KVD * DIMn];
__device__ __align__(16) __nv_bfloat16 g_wvh[(size_t)KVD * DIMn],  g_wvl[(size_t)KVD * DIMn];
__device__ __align__(16) __nv_bfloat16 g_wph[(size_t)DIMn * DIMn], g_wpl[(size_t)DIMn * DIMn];
__device__ __align__(16) __nv_bfloat16 g_yh[(size_t)NTOK * DIMn],  g_yl[(size_t)NTOK * DIMn];
// flash operands (normed Q/K, V) split hi/lo
__device__ __align__(16) __nv_bfloat16 g_qh2[(size_t)NTOK * DIMn], g_ql2[(size_t)NTOK * DIMn];
__device__ __align__(16) __nv_bfloat16 g_kh2[(size_t)NTOK * KVD],  g_kl2[(size_t)NTOK * KVD];
__device__ __align__(16) __nv_bfloat16 g_vh2[(size_t)NTOK * KVD],  g_vl2[(size_t)NTOK * KVD];

// ---------------- PTX helpers (portable, no arch-specific features) -------
__device__ __forceinline__ uint32_t smem_u32(const void* p) {
    uint32_t a;
    asm("{ .reg .u64 t; cvta.to.shared.u64 t, %1; cvt.u32.u64 %0, t; }" : "=r"(a) : "l"(p));
    return a;
}
__device__ __forceinline__ float ex2(float x) {
    float r; asm("ex2.approx.ftz.f32 %0, %1;" : "=f"(r) : "f"(x)); return r;
}
__device__ __forceinline__ void cpa16(uint32_t dst_smem, const void* src_gmem) {
    asm volatile("cp.async.cg.shared.global [%0], [%1], 16;" :: "r"(dst_smem), "l"(src_gmem));
}
#define CP_COMMIT()  asm volatile("cp.async.commit_group;" ::: "memory")
#define CP_WAIT0()   asm volatile("cp.async.wait_group 0;" ::: "memory")
#define CP_WAIT1()   asm volatile("cp.async.wait_group 1;" ::: "memory")

__device__ __forceinline__ void ldsm4(uint32_t* r, uint32_t addr) {
    asm volatile("ldmatrix.sync.aligned.m8n8.x4.shared.b16 {%0,%1,%2,%3}, [%4];"
        : "=r"(r[0]), "=r"(r[1]), "=r"(r[2]), "=r"(r[3]) : "r"(addr));
}
__device__ __forceinline__ void ldsm4t(uint32_t* r, uint32_t addr) {
    asm volatile("ldmatrix.sync.aligned.m8n8.x4.trans.shared.b16 {%0,%1,%2,%3}, [%4];"
        : "=r"(r[0]), "=r"(r[1]), "=r"(r[2]), "=r"(r[3]) : "r"(addr));
}
__device__ __forceinline__ void mma16816(float* d, const uint32_t* a, const uint32_t* b) {
    asm volatile("mma.sync.aligned.m16n8k16.row.col.f32.bf16.bf16.f32 "
        "{%0,%1,%2,%3}, {%4,%5,%6,%7}, {%8,%9}, {%0,%1,%2,%3};"
        : "+f"(d[0]), "+f"(d[1]), "+f"(d[2]), "+f"(d[3])
        : "r"(a[0]), "r"(a[1]), "r"(a[2]), "r"(a[3]), "r"(b[0]), "r"(b[1]));
}
// pack two fp32 into one bf16x2 reg (low = x, high = y) and its residual
__device__ __forceinline__ void split_pack2(float x, float y, uint32_t& hi, uint32_t& lo) {
    __nv_bfloat16 hx = __float2bfloat16(x), hy = __float2bfloat16(y);
    float lx = x - __bfloat162float(hx), ly = y - __bfloat162float(hy);
    __nv_bfloat162 hv(hx, hy);
    __nv_bfloat162 lv(__float2bfloat16(lx), __float2bfloat16(ly));
    hi = *reinterpret_cast<uint32_t*>(&hv);
    lo = *reinterpret_cast<uint32_t*>(&lv);
}

#define SW128(off) ((off) ^ (((off) >> 3) & 0x70))

// ---------------- RoPE table (NTK-scaled, T > train_seq_len) --------------
__global__ void rope_table_kernel() {
    int idx = blockIdx.x * blockDim.x + threadIdx.x;
    if (idx >= TT * HALF) return;
    int t = idx >> 6;
    int i = idx & 63;
    double base = 10000.0 * pow(2.0, 128.0 / 126.0);
    double inv  = pow(base, -((double)(2 * i)) / 128.0);
    double ang  = (double)t * inv;
    g_cos[idx] = (float)cos(ang);
    g_sin[idx] = (float)sin(ang);
}

// ---------------- fp32 -> bf16 hi/lo split --------------------------------
__global__ void split_kernel(const float* __restrict__ x,
                             __nv_bfloat16* __restrict__ hi,
                             __nv_bfloat16* __restrict__ lo, int n4) {
    int i = blockIdx.x * blockDim.x + threadIdx.x;
    if (i >= n4) return;
    float4 v = ((const float4*)x)[i];
    __nv_bfloat16 h0 = __float2bfloat16(v.x);
    __nv_bfloat16 h1 = __float2bfloat16(v.y);
    __nv_bfloat16 h2 = __float2bfloat16(v.z);
    __nv_bfloat16 h3 = __float2bfloat16(v.w);
    __nv_bfloat16 l0 = __float2bfloat16(v.x - __bfloat162float(h0));
    __nv_bfloat16 l1 = __float2bfloat16(v.y - __bfloat162float(h1));
    __nv_bfloat16 l2 = __float2bfloat16(v.z - __bfloat162float(h2));
    __nv_bfloat16 l3 = __float2bfloat16(v.w - __bfloat162float(h3));
    ((__nv_bfloat162*)hi)[2 * i]     = __nv_bfloat162(h0, h1);
    ((__nv_bfloat162*)hi)[2 * i + 1] = __nv_bfloat162(h2, h3);
    ((__nv_bfloat162*)lo)[2 * i]     = __nv_bfloat162(l0, l1);
    ((__nv_bfloat162*)lo)[2 * i + 1] = __nv_bfloat162(l2, l3);
}

// ---------------- bf16-split GEMM on mma.sync (HMMA) ----------------------
#define GS_ARR    16384
#define GS_STAGE  (4 * GS_ARR)
#define GEMM_SMEM (2 * GS_STAGE)

__device__ __forceinline__ void gemm_fill_stage(
    uint32_t stage, const __nv_bfloat16* const* src, int rowA, int rowB,
    int ck, int K, int tid)
{
#pragma unroll
    for (int it = 0; it < 16; it++) {
        int idx = tid + it * 256;              // 0..4095
        int arr = idx >> 10;                   // 0..3
        int r   = (idx >> 3) & 127;            // row in tile
        int p   = idx & 7;                     // 16B piece in row
        uint32_t off = SW128((uint32_t)(r * 128 + p * 16));
        int grow = ((arr < 2) ? rowA : rowB) + r;
        const __nv_bfloat16* g = src[arr] + (size_t)grow * K + ck * 64 + p * 8;
        cpa16(stage + arr * GS_ARR + off, g);
    }
    CP_COMMIT();
}

__device__ __forceinline__ void mma_gemm_body(
    const __nv_bfloat16* __restrict__ Ah, const __nv_bfloat16* __restrict__ Al,
    const __nv_bfloat16* __restrict__ Bh, const __nv_bfloat16* __restrict__ Bl,
    float* __restrict__ C, int K, int ldc, int rowA, int rowB, uint32_t sb)
{
    const int tid = threadIdx.x;
    const int wid = tid >> 5;
    const int lane = tid & 31;
    const int wm = wid & 3;
    const int wn = wid >> 2;

    const __nv_bfloat16* src[4] = {Ah, Al, Bh, Bl};

    float accf[2][8][4];
#pragma unroll
    for (int mb = 0; mb < 2; mb++)
#pragma unroll
        for (int nb = 0; nb < 8; nb++)
#pragma unroll
            for (int j = 0; j < 4; j++) accf[mb][nb][j] = 0.f;

    const int KT = K >> 6;
    gemm_fill_stage(sb, src, rowA, rowB, 0, K, tid);
    gemm_fill_stage(sb + GS_STAGE, src, rowA, rowB, 1, K, tid);

    const int aRow = wm * 32 + ((lane >> 3) & 1) * 8 + (lane & 7);
    const int aCol = (lane >> 4);
    const int bRow = wn * 64 + (lane >> 4) * 8 + (lane & 7);
    const int bCol = ((lane >> 3) & 1);

    for (int ck = 0; ck < KT; ck++) {
        if (ck + 2 <= KT) CP_WAIT1(); else CP_WAIT0();
        __syncthreads();
        const uint32_t stage = sb + (ck & 1) * GS_STAGE;

        const uint32_t aoff[3] = {0u, 0u, (uint32_t)GS_ARR};
        const uint32_t boff[3] = {2u * GS_ARR, 3u * GS_ARR, 2u * GS_ARR};
#pragma unroll
        for (int pass = 0; pass < 3; pass++) {
            const uint32_t aBase = stage + aoff[pass];
            const uint32_t bBase = stage + boff[pass];
#pragma unroll
            for (int kk = 0; kk < 4; kk++) {
                uint32_t a[2][4];
#pragma unroll
                for (int mb = 0; mb < 2; mb++) {
                    uint32_t addr = aBase +
                        SW128((uint32_t)((aRow + mb * 16) * 128 + (aCol + kk * 2) * 16));
                    ldsm4(a[mb], addr);
                }
                uint32_t b[4][4];
#pragma unroll
                for (int nb4 = 0; nb4 < 4; nb4++) {
                    uint32_t addr = bBase +
                        SW128((uint32_t)((bRow + nb4 * 16) * 128 + (bCol + kk * 2) * 16));
                    ldsm4(b[nb4], addr);
                }
#pragma unroll
                for (int mb = 0; mb < 2; mb++)
#pragma unroll
                    for (int nb = 0; nb < 8; nb++)
                        mma16816(accf[mb][nb], a[mb], &b[nb >> 1][(nb & 1) * 2]);
            }
        }
        __syncthreads();
        if (ck + 2 < KT)
            gemm_fill_stage(stage, src, rowA, rowB, ck + 2, K, tid);
    }

    const int g = lane >> 2;
    const int t2 = (lane & 3) * 2;
#pragma unroll
    for (int mb = 0; mb < 2; mb++) {
        int r0 = rowA + wm * 32 + mb * 16 + g;
#pragma unroll
        for (int nb = 0; nb < 8; nb++) {
            int col = rowB + wn * 64 + nb * 8 + t2;
            float* c0 = C + (size_t)r0 * ldc + col;
            float* c1 = C + (size_t)(r0 + 8) * ldc + col;
            c0[0] = accf[mb][nb][0]; c0[1] = accf[mb][nb][1];
            c1[0] = accf[mb][nb][2]; c1[1] = accf[mb][nb][3];
        }
    }
}

__global__ __launch_bounds__(256, 1)
void mma_gemm(const __nv_bfloat16* __restrict__ Ah, const __nv_bfloat16* __restrict__ Al,
              const __nv_bfloat16* __restrict__ Bh, const __nv_bfloat16* __restrict__ Bl,
              float* __restrict__ C, int K, int ldc) {
    extern __shared__ char smc[];
    mma_gemm_body(Ah, Al, Bh, Bl, C, K, ldc,
                  blockIdx.y * 128, blockIdx.x * 128, smem_u32(smc));
}

__global__ __launch_bounds__(256, 1)
void mma_gemm_kv(const __nv_bfloat16* __restrict__ xh, const __nv_bfloat16* __restrict__ xl,
                 const __nv_bfloat16* __restrict__ wkh, const __nv_bfloat16* __restrict__ wkl,
                 const __nv_bfloat16* __restrict__ wvh, const __nv_bfloat16* __restrict__ wvl,
                 float* __restrict__ Ck, float* __restrict__ Cv) {
    extern __shared__ char smc[];
    int nb = blockIdx.x;
    const __nv_bfloat16 *bh, *bl;
    float* C;
    if (nb < 4) { bh = wkh; bl = wkl; C = Ck; }
    else        { bh = wvh; bl = wvl; C = Cv; nb -= 4; }
    mma_gemm_body(xh, xl, bh, bl, C, DIMn, KVD,
                  blockIdx.y * 128, nb * 128, smem_u32(smc));
}

// ---------------- fused RMSNorm + RoPE (+ head gain, + extra scale) -------
__global__ void normrope_kernel(float* __restrict__ X, int heads,
                                const float* __restrict__ gain, int use_gain,
                                float scale) {
    const int row = blockIdx.x;
    const int h = blockIdx.y;
    const int d = threadIdx.x;
    const int ld = heads * DD;
    float* p = X + (size_t)row * ld + h * DD;

    float v = p[d];
    __shared__ float sh[DD];
    __shared__ float red[4];
    float sq = v * v;
#pragma unroll
    for (int o = 16; o; o >>= 1) sq += __shfl_xor_sync(0xffffffffu, sq, o);
    if ((d & 31) == 0) red[d >> 5] = sq;
    __syncthreads();
    float tot = red[0] + red[1] + red[2] + red[3];
    float r = rsqrtf(tot * (1.0f / DD) + 1.1920929e-7f);
    sh[d] = v * r;
    __syncthreads();
    if (d < HALF) {
        int t = row & (TT - 1);
        float c = g_cos[t * HALF + d];
        float s = g_sin[t * HALF + d];
        float x1 = sh[d], x2 = sh[d + HALF];
        float gg = (use_gain ? gain[h] : 1.0f) * scale;
        p[d]        = (x1 * c + x2 * s) * gg;
        p[d + HALF] = (-x1 * s + x2 * c) * gg;
    }
}

// ---------------- HMMA flash attention (causal, GQA) ----------------------
// BM=128 (8 warps x 16 rows), BN=64. bf16 hi/lo split operands.
// S: 3 passes (QhKh, QhKl, QlKh). PV: 3 passes (PhVh, PhVl, PlVh).
// smem: Q 4x16KB resident + K/V 2 stages x 8 arrays x 8KB = 192KB.
#define FL_BM 128
#define FL_BN 64
#define FQ_ARR  16384
#define FKV_ARR 8192
#define FKV_OFF 65536
#define FKV_STAGE 65536
#define FLM_SMEM (FKV_OFF + 2 * FKV_STAGE)

__global__ __launch_bounds__(256, 1)
void flash_mma_kernel(const __nv_bfloat16* __restrict__ Qh, const __nv_bfloat16* __restrict__ Ql,
                      const __nv_bfloat16* __restrict__ Kh, const __nv_bfloat16* __restrict__ Kl,
                      const __nv_bfloat16* __restrict__ Vh, const __nv_bfloat16* __restrict__ Vl,
                      float* __restrict__ O) {
    extern __shared__ char smc[];
    const uint32_t sb = smem_u32(smc);
    const int qb = (gridDim.x - 1) - blockIdx.x;   // big tiles first
    const int bh = blockIdx.y;
    const int b = bh / HH, h = bh % HH, kh = h / GG;
    const int q0 = qb * FL_BM;
    const int tid = threadIdx.x;
    const int wid = tid >> 5, lane = tid & 31;

    // K/V global bases: arrays 0-3 = Kh0,Kh1,Kl0,Kl1 ; 4-7 = Vh0,Vh1,Vl0,Vl1
    const __nv_bfloat16* kvsrc[8];
    {
        size_t koff = (size_t)(b * TT) * KVD + kh * DD;
        kvsrc[0] = Kh + koff; kvsrc[1] = Kh + koff + 64;
        kvsrc[2] = Kl + koff; kvsrc[3] = Kl + koff + 64;
        kvsrc[4] = Vh + koff; kvsrc[5] = Vh + koff + 64;
        kvsrc[6] = Vl + koff; kvsrc[7] = Vl + koff + 64;
    }
    auto fill_kv = [&](int blk, int s) {
#pragma unroll
        for (int it = 0; it < 16; it++) {
            int idx = tid + it * 256;
            int arr = idx >> 9, r = (idx >> 3) & 63, p = idx & 7;
            cpa16(sb + FKV_OFF + s * FKV_STAGE + arr * FKV_ARR +
                      SW128((uint32_t)(r * 128 + p * 16)),
                  kvsrc[arr] + (size_t)(blk * FL_BN + r) * KVD + p * 8);
        }
        CP_COMMIT();
    };

    // prologue: Q (arrays Qh0,Qh1,Ql0,Ql1) + KV stage 0 (one group), KV stage 1
    {
        const __nv_bfloat16* qsrc[4];
        size_t qoff = (size_t)(b * TT + q0) * DIMn + h * DD;
        qsrc[0] = Qh + qoff; qsrc[1] = Qh + qoff + 64;
        qsrc[2] = Ql + qoff; qsrc[3] = Ql + qoff + 64;
#pragma unroll
        for (int it = 0; it < 16; it++) {
            int idx = tid + it * 256;
            int arr = idx >> 10, r = (idx >> 3) & 127, p = idx & 7;
            cpa16(sb + arr * FQ_ARR + SW128((uint32_t)(r * 128 + p * 16)),
                  qsrc[arr] + (size_t)r * DIMn + p * 8);
        }
    }
    const int nkb = 2 * qb + 2;
    fill_kv(0, 0);                   // commits Q + KV0 together
    if (nkb > 1) fill_kv(1, 1);

    // fragment lane addressing
    const int aRowOff = ((lane >> 3) & 1) * 8 + (lane & 7);   // + wid*16
    const int aPiece  = lane >> 4;                            // + kk*2
    const int bRowOff = (lane >> 4) * 8 + (lane & 7);         // + nt*16
    const int bPiece  = (lane >> 3) & 1;                      // + kk*2
    const int vRowOff = ((lane >> 3) & 1) * 8 + (lane & 7);   // + kk*16
    const int vPiece  = lane >> 4;                            // + dt*2

    float m0 = -INFINITY, m1 = -INFINITY, l0 = 0.f, l1 = 0.f;
    float oacc[16][4];
#pragma unroll
    for (int i = 0; i < 16; i++)
#pragma unroll
        for (int j = 0; j < 4; j++) oacc[i][j] = 0.f;

    for (int kb = 0; kb < nkb; kb++) {
        if (kb + 1 < nkb) CP_WAIT1(); else CP_WAIT0();
        __syncthreads();
        const uint32_t kvb = sb + FKV_OFF + (kb & 1) * FKV_STAGE;

        // ---- S = Q K^T (3 split passes), fp32 accum ----
        float sacc[8][4];
#pragma unroll
        for (int i = 0; i < 8; i++)
#pragma unroll
            for (int j = 0; j < 4; j++) sacc[i][j] = 0.f;

        const uint32_t qsel[3] = {0u, 0u, 2u * FQ_ARR};
        const uint32_t ksel[3] = {0u, 2u * FKV_ARR, 0u};
#pragma unroll
        for (int pass = 0; pass < 3; pass++) {
            const uint32_t qbs = sb + qsel[pass];
            const uint32_t kbs = kvb + ksel[pass];
#pragma unroll
            for (int half = 0; half < 2; half++) {
                const uint32_t qa = qbs + half * FQ_ARR;
                const uint32_t ka = kbs + half * FKV_ARR;
#pragma unroll
                for (int kk = 0; kk < 4; kk++) {
                    uint32_t a[4];
                    ldsm4(a, qa + SW128((uint32_t)((wid * 16 + aRowOff) * 128 +
                                                   (aPiece + kk * 2) * 16)));
#pragma unroll
                    for (int nt = 0; nt < 4; nt++) {
                        uint32_t bb[4];
                        ldsm4(bb, ka + SW128((uint32_t)((nt * 16 + bRowOff) * 128 +
                                                        (bPiece + kk * 2) * 16)));
                        mma16816(sacc[nt * 2],     a, bb);
                        mma16816(sacc[nt * 2 + 1], a, bb + 2);
                    }
                }
            }
        }

        // ---- causal mask on fragments ----
        const int k0 = kb * FL_BN;
        const int row0 = q0 + wid * 16 + (lane >> 2);
        if (kb >= 2 * qb) {
#pragma unroll
            for (int nt = 0; nt < 8; nt++) {
                int c = k0 + nt * 8 + (lane & 3) * 2;
                if (c > row0)         sacc[nt][0] = -INFINITY;
                if (c + 1 > row0)     sacc[nt][1] = -INFINITY;
                if (c > row0 + 8)     sacc[nt][2] = -INFINITY;
                if (c + 1 > row0 + 8) sacc[nt][3] = -INFINITY;
            }
        }

        // ---- online softmax (exp2 domain; scale folded into Q) ----
        float mx0 = sacc[0][0], mx1 = sacc[0][2];
#pragma unroll
        for (int nt = 0; nt < 8; nt++) {
            mx0 = fmaxf(mx0, fmaxf(sacc[nt][0], sacc[nt][1]));
            mx1 = fmaxf(mx1, fmaxf(sacc[nt][2], sacc[nt][3]));
        }
        mx0 = fmaxf(mx0, __shfl_xor_sync(0xffffffffu, mx0, 1));
        mx0 = fmaxf(mx0, __shfl_xor_sync(0xffffffffu, mx0, 2));
        mx1 = fmaxf(mx1, __shfl_xor_sync(0xffffffffu, mx1, 1));
        mx1 = fmaxf(mx1, __shfl_xor_sync(0xffffffffu, mx1, 2));
        float mn0 = fmaxf(m0, mx0), mn1 = fmaxf(m1, mx1);
        float al0 = ex2(m0 - mn0), al1 = ex2(m1 - mn1);
        m0 = mn0; m1 = mn1;
        float s0 = 0.f, s1 = 0.f;
#pragma unroll
        for (int nt = 0; nt < 8; nt++) {
            float p0 = ex2(sacc[nt][0] - mn0); sacc[nt][0] = p0; s0 += p0;
            float p1 = ex2(sacc[nt][1] - mn0); sacc[nt][1] = p1; s0 += p1;
            float p2 = ex2(sacc[nt][2] - mn1); sacc[nt][2] = p2; s1 += p2;
            float p3 = ex2(sacc[nt][3] - mn1); sacc[nt][3] = p3; s1 += p3;
        }
        s0 += __shfl_xor_sync(0xffffffffu, s0, 1);
        s0 += __shfl_xor_sync(0xffffffffu, s0, 2);
        s1 += __shfl_xor_sync(0xffffffffu, s1, 1);
        s1 += __shfl_xor_sync(0xffffffffu, s1, 2);
        l0 = l0 * al0 + s0;
        l1 = l1 * al1 + s1;
#pragma unroll
        for (int ot = 0; ot < 16; ot++) {
            oacc[ot][0] *= al0; oacc[ot][1] *= al0;
            oacc[ot][2] *= al1; oacc[ot][3] *= al1;
        }

        // ---- O += P V (3 split passes) ----
#pragma unroll
        for (int kk = 0; kk < 4; kk++) {
            uint32_t pha[4], pla[4];
            split_pack2(sacc[2 * kk][0],     sacc[2 * kk][1],     pha[0], pla[0]);
            split_pack2(sacc[2 * kk][2],     sacc[2 * kk][3],     pha[1], pla[1]);
            split_pack2(sacc[2 * kk + 1][0], sacc[2 * kk + 1][1], pha[2], pla[2]);
            split_pack2(sacc[2 * kk + 1][2], sacc[2 * kk + 1][3], pha[3], pla[3]);
#pragma unroll
            for (int half = 0; half < 2; half++) {
                const uint32_t vha = kvb + (4 + half) * FKV_ARR;
                const uint32_t vla = kvb + (6 + half) * FKV_ARR;
#pragma unroll
                for (int dt = 0; dt < 4; dt++) {
                    uint32_t aoff = SW128((uint32_t)((kk * 16 + vRowOff) * 128 +
                                                     (dt * 2 + vPiece) * 16));
                    uint32_t bh_[4], bl_[4];
                    ldsm4t(bh_, vha + aoff);
                    ldsm4t(bl_, vla + aoff);
                    const int ot = half * 8 + dt * 2;
                    mma16816(oacc[ot],     pha, bh_);
                    mma16816(oacc[ot + 1], pha, bh_ + 2);
                    mma16816(oacc[ot],     pha, bl_);
                    mma16816(oacc[ot + 1], pha, bl_ + 2);
                    mma16816(oacc[ot],     pla, bh_);
                    mma16816(oacc[ot + 1], pla, bh_ + 2);
                }
            }
        }

        __syncthreads();
        if (kb + 2 < nkb) fill_kv(kb + 2, kb & 1);
    }

    // ---- epilogue ----
    const float inv0 = 1.f / l0, inv1 = 1.f / l1;
    const int rg = b * TT + q0 + wid * 16 + (lane >> 2);
    float* o0 = O + (size_t)rg * DIMn + h * DD + (lane & 3) * 2;
    float* o1 = o0 + (size_t)8 * DIMn;
#pragma unroll
    for (int ot = 0; ot < 16; ot++) {
        int d = (ot >> 3) * 64 + ((ot >> 1) & 3) * 16 + (ot & 1) * 8;
        *(float2*)(o0 + d) = make_float2(oacc[ot][0] * inv0, oacc[ot][1] * inv0);
        *(float2*)(o1 + d) = make_float2(oacc[ot][2] * inv1, oacc[ot][3] * inv1);
    }
}

// ---------------- host launcher ----------------
extern "C" void kernel_launch(void* const* d_in, const int* in_sizes, int n_in,
                              void* d_out, int out_size) {
    const float* x     = (const float*)d_in[0];
    const float* Wq    = (const float*)d_in[1];
    const float* Wk    = (const float*)d_in[2];
    const float* Wv    = (const float*)d_in[3];
    const float* Wproj = (const float*)d_in[4];
    const float* qgain = (const float*)d_in[5];
    float* out = (float*)d_out;

    float *q_ptr, *k_ptr, *y_ptr;
    cudaGetSymbolAddress((void**)&q_ptr, g_Q);
    cudaGetSymbolAddress((void**)&k_ptr, g_K);
    cudaGetSymbolAddress((void**)&y_ptr, g_Y);
    __nv_bfloat16 *xh, *xl, *wqh, *wql, *wkh, *wkl, *wvh, *wvl, *wph, *wpl, *yh, *yl;
    __nv_bfloat16 *qh2, *ql2, *kh2, *kl2, *vh2, *vl2;
    cudaGetSymbolAddress((void**)&xh, g_xh);   cudaGetSymbolAddress((void**)&xl, g_xl);
    cudaGetSymbolAddress((void**)&wqh, g_wqh); cudaGetSymbolAddress((void**)&wql, g_wql);
    cudaGetSymbolAddress((void**)&wkh, g_wkh); cudaGetSymbolAddress((void**)&wkl, g_wkl);
    cudaGetSymbolAddress((void**)&wvh, g_wvh); cudaGetSymbolAddress((void**)&wvl, g_wvl);
    cudaGetSymbolAddress((void**)&wph, g_wph); cudaGetSymbolAddress((void**)&wpl, g_wpl);
    cudaGetSymbolAddress((void**)&yh, g_yh);   cudaGetSymbolAddress((void**)&yl, g_yl);
    cudaGetSymbolAddress((void**)&qh2, g_qh2); cudaGetSymbolAddress((void**)&ql2, g_ql2);
    cudaGetSymbolAddress((void**)&kh2, g_kh2); cudaGetSymbolAddress((void**)&kl2, g_kl2);
    cudaGetSymbolAddress((void**)&vh2, g_vh2); cudaGetSymbolAddress((void**)&vl2, g_vl2);

    float* v_out = out + (size_t)NTOK * DIMn;   // v is the second output

    cudaFuncSetAttribute(mma_gemm, cudaFuncAttributeMaxDynamicSharedMemorySize, GEMM_SMEM);
    cudaFuncSetAttribute(mma_gemm_kv, cudaFuncAttributeMaxDynamicSharedMemorySize, GEMM_SMEM);
    cudaFuncSetAttribute(flash_mma_kernel, cudaFuncAttributeMaxDynamicSharedMemorySize, FLM_SMEM);

    const float qscale = 0.08838834764831845f * 1.4426950408889634f;  // 1/sqrt(D)*log2(e)

    // 1. RoPE tables + operand splits
    rope_table_kernel<<<(TT * HALF + 255) / 256, 256>>>();
    split_kernel<<<(NTOK * DIMn / 4 + 255) / 256, 256>>>(x, xh, xl, NTOK * DIMn / 4);
    split_kernel<<<(DIMn * DIMn / 4 + 255) / 256, 256>>>(Wq, wqh, wql, DIMn * DIMn / 4);
    split_kernel<<<(KVD * DIMn / 4 + 255) / 256, 256>>>(Wk, wkh, wkl, KVD * DIMn / 4);
    split_kernel<<<(KVD * DIMn / 4 + 255) / 256, 256>>>(Wv, wvh, wvl, KVD * DIMn / 4);
    split_kernel<<<(DIMn * DIMn / 4 + 255) / 256, 256>>>(Wproj, wph, wpl, DIMn * DIMn / 4);

    // 2. QKV projections on HMMA (V written directly into output tail; K/V fused)
    mma_gemm<<<dim3(DIMn / 128, NTOK / 128), 256, GEMM_SMEM>>>(xh, xl, wqh, wql, q_ptr, DIMn, DIMn);
    mma_gemm_kv<<<dim3(8, NTOK / 128), 256, GEMM_SMEM>>>(xh, xl, wkh, wkl, wvh, wvl, k_ptr, v_out);

    // 3. RMSNorm + RoPE (+ q gain, with attention scale folded into Q)
    normrope_kernel<<<dim3(NTOK, HH), 128>>>(q_ptr, HH, qgain, 1, qscale);
    normrope_kernel<<<dim3(NTOK, HKVn), 128>>>(k_ptr, HKVn, nullptr, 0, 1.0f);

    // 4. split flash operands to bf16 hi/lo
    split_kernel<<<(NTOK * DIMn / 4 + 255) / 256, 256>>>(q_ptr, qh2, ql2, NTOK * DIMn / 4);
    split_kernel<<<(NTOK * KVD / 4 + 255) / 256, 256>>>(k_ptr, kh2, kl2, NTOK * KVD / 4);
    split_kernel<<<(NTOK * KVD / 4 + 255) / 256, 256>>>(v_out, vh2, vl2, NTOK * KVD / 4);

    // 5. causal GQA flash attention on HMMA
    flash_mma_kernel<<<dim3(TT / FL_BM, BB * HH), 256, FLM_SMEM>>>(
        qh2, ql2, kh2, kl2, vh2, vl2, y_ptr);

    // 6. output projection on HMMA
    split_kernel<<<(NTOK * DIMn / 4 + 255) / 256, 256>>>(y_ptr, yh, yl, NTOK * DIMn / 4);
    mma_gemm<<<dim3(DIMn / 128, NTOK / 128), 256, GEMM_SMEM>>>(yh, yl, wph, wpl, out, DIMn, DIMn);
}

// round 13
// speedup vs baseline: 6.1228x; 1.1632x over previous
#include <cuda_runtime.h>
#include <cuda_bf16.h>
#include <math.h>
#include <stdint.h>

// ---------------- problem constants ----------------
#define BB   2
#define TT   2048
#define HH   16
#define HKVn 4
#define DD   128
#define GG   4
#define DIMn 2048           // HH*DD
#define KVD  512            // HKVn*DD
#define NTOK (BB*TT)        // 4096
#define HALF 64             // DD/2

// ---------------- device scratch (no allocs allowed) ----------------
__device__ float g_Q[(size_t)NTOK * DIMn];     // fp32 Q proj (pre-norm)
__device__ float g_K[(size_t)NTOK * KVD];      // fp32 K proj (pre-norm)
__device__ float g_cos[TT * HALF];
__device__ float g_sin[TT * HALF];
// bf16 hi/lo split operands (16B-aligned for cp.async)
__device__ __align__(16) __nv_bfloat16 g_xh[(size_t)NTOK * DIMn], g_xl[(size_t)NTOK * DIMn];
__device__ __align__(16) __nv_bfloat16 g_wqh[(size_t)DIMn * DIMn], g_wql[(size_t)DIMn * DIMn];
__device__ __align__(16) __nv_bfloat16 g_wkh[(size_t)KVD * DIMn],  g_wkl[(size_t)KVD * DIMn];
__device__ __align__(16) __nv_bfloat16 g_wvh[(size_t)KVD * DIMn],  g_wvl[(size_t)KVD * DIMn];
__device__ __align__(16) __nv_bfloat16 g_wph[(size_t)DIMn * DIMn], g_wpl[(size_t)DIMn * DIMn];
__device__ __align__(16) __nv_bfloat16 g_yh[(size_t)NTOK * DIMn],  g_yl[(size_t)NTOK * DIMn];
// flash operands (normed Q/K, V) split hi/lo
__device__ __align__(16) __nv_bfloat16 g_qh2[(size_t)NTOK * DIMn], g_ql2[(size_t)NTOK * DIMn];
__device__ __align__(16) __nv_bfloat16 g_kh2[(size_t)NTOK * KVD],  g_kl2[(size_t)NTOK * KVD];
__device__ __align__(16) __nv_bfloat16 g_vh2[(size_t)NTOK * KVD],  g_vl2[(size_t)NTOK * KVD];

// ---------------- PTX helpers (portable, no arch-specific features) -------
__device__ __forceinline__ uint32_t smem_u32(const void* p) {
    uint32_t a;
    asm("{ .reg .u64 t; cvta.to.shared.u64 t, %1; cvt.u32.u64 %0, t; }" : "=r"(a) : "l"(p));
    return a;
}
__device__ __forceinline__ float ex2(float x) {
    float r; asm("ex2.approx.ftz.f32 %0, %1;" : "=f"(r) : "f"(x)); return r;
}
__device__ __forceinline__ void cpa16(uint32_t dst_smem, const void* src_gmem) {
    asm volatile("cp.async.cg.shared.global [%0], [%1], 16;" :: "r"(dst_smem), "l"(src_gmem));
}
#define CP_COMMIT()  asm volatile("cp.async.commit_group;" ::: "memory")
#define CP_WAIT0()   asm volatile("cp.async.wait_group 0;" ::: "memory")
#define CP_WAIT1()   asm volatile("cp.async.wait_group 1;" ::: "memory")

__device__ __forceinline__ void ldsm4(uint32_t* r, uint32_t addr) {
    asm volatile("ldmatrix.sync.aligned.m8n8.x4.shared.b16 {%0,%1,%2,%3}, [%4];"
        : "=r"(r[0]), "=r"(r[1]), "=r"(r[2]), "=r"(r[3]) : "r"(addr));
}
__device__ __forceinline__ void ldsm4t(uint32_t* r, uint32_t addr) {
    asm volatile("ldmatrix.sync.aligned.m8n8.x4.trans.shared.b16 {%0,%1,%2,%3}, [%4];"
        : "=r"(r[0]), "=r"(r[1]), "=r"(r[2]), "=r"(r[3]) : "r"(addr));
}
__device__ __forceinline__ void mma16816(float* d, const uint32_t* a, const uint32_t* b) {
    asm volatile("mma.sync.aligned.m16n8k16.row.col.f32.bf16.bf16.f32 "
        "{%0,%1,%2,%3}, {%4,%5,%6,%7}, {%8,%9}, {%0,%1,%2,%3};"
        : "+f"(d[0]), "+f"(d[1]), "+f"(d[2]), "+f"(d[3])
        : "r"(a[0]), "r"(a[1]), "r"(a[2]), "r"(a[3]), "r"(b[0]), "r"(b[1]));
}
// pack two fp32 into one bf16x2 reg (low = x, high = y) and its residual
__device__ __forceinline__ void split_pack2(float x, float y, uint32_t& hi, uint32_t& lo) {
    __nv_bfloat16 hx = __float2bfloat16(x), hy = __float2bfloat16(y);
    float lx = x - __bfloat162float(hx), ly = y - __bfloat162float(hy);
    __nv_bfloat162 hv(hx, hy);
    __nv_bfloat162 lv(__float2bfloat16(lx), __float2bfloat16(ly));
    hi = *reinterpret_cast<uint32_t*>(&hv);
    lo = *reinterpret_cast<uint32_t*>(&lv);
}
__device__ __forceinline__ void store_split2(__nv_bfloat16* H, __nv_bfloat16* L,
                                             size_t idx, float x, float y) {
    uint32_t hi, lo;
    split_pack2(x, y, hi, lo);
    *(uint32_t*)(H + idx) = hi;
    *(uint32_t*)(L + idx) = lo;
}

#define SW128(off) ((off) ^ (((off) >> 3) & 0x70))

// ---------------- RoPE table (NTK-scaled, T > train_seq_len) --------------
__global__ void rope_table_kernel() {
    int idx = blockIdx.x * blockDim.x + threadIdx.x;
    if (idx >= TT * HALF) return;
    int t = idx >> 6;
    int i = idx & 63;
    double base = 10000.0 * pow(2.0, 128.0 / 126.0);
    double inv  = pow(base, -((double)(2 * i)) / 128.0);
    double ang  = (double)t * inv;
    g_cos[idx] = (float)cos(ang);
    g_sin[idx] = (float)sin(ang);
}

// ---------------- fp32 -> bf16 hi/lo split --------------------------------
__global__ void split_kernel(const float* __restrict__ x,
                             __nv_bfloat16* __restrict__ hi,
                             __nv_bfloat16* __restrict__ lo, int n4) {
    int i = blockIdx.x * blockDim.x + threadIdx.x;
    if (i >= n4) return;
    float4 v = ((const float4*)x)[i];
    __nv_bfloat16 h0 = __float2bfloat16(v.x);
    __nv_bfloat16 h1 = __float2bfloat16(v.y);
    __nv_bfloat16 h2 = __float2bfloat16(v.z);
    __nv_bfloat16 h3 = __float2bfloat16(v.w);
    __nv_bfloat16 l0 = __float2bfloat16(v.x - __bfloat162float(h0));
    __nv_bfloat16 l1 = __float2bfloat16(v.y - __bfloat162float(h1));
    __nv_bfloat16 l2 = __float2bfloat16(v.z - __bfloat162float(h2));
    __nv_bfloat16 l3 = __float2bfloat16(v.w - __bfloat162float(h3));
    ((__nv_bfloat162*)hi)[2 * i]     = __nv_bfloat162(h0, h1);
    ((__nv_bfloat162*)hi)[2 * i + 1] = __nv_bfloat162(h2, h3);
    ((__nv_bfloat162*)lo)[2 * i]     = __nv_bfloat162(l0, l1);
    ((__nv_bfloat162*)lo)[2 * i + 1] = __nv_bfloat162(l2, l3);
}

// ---------------- bf16-split GEMM on mma.sync (HMMA) ----------------------
// C = (Ah+Al)(Bh+Bl)^T, 3 products (hh, hl, lh) with fragment reuse:
// all 12 fragments loaded once per kk-step, 48 MMAs issued per load group.
#define GS_ARR    16384
#define GS_STAGE  (4 * GS_ARR)
#define GEMM_SMEM (2 * GS_STAGE)

__device__ __forceinline__ void gemm_fill_stage(
    uint32_t stage, const __nv_bfloat16* const* src, int rowA, int rowB,
    int ck, int K, int tid)
{
#pragma unroll
    for (int it = 0; it < 16; it++) {
        int idx = tid + it * 256;              // 0..4095
        int arr = idx >> 10;                   // 0..3
        int r   = (idx >> 3) & 127;            // row in tile
        int p   = idx & 7;                     // 16B piece in row
        uint32_t off = SW128((uint32_t)(r * 128 + p * 16));
        int grow = ((arr < 2) ? rowA : rowB) + r;
        const __nv_bfloat16* g = src[arr] + (size_t)grow * K + ck * 64 + p * 8;
        cpa16(stage + arr * GS_ARR + off, g);
    }
    CP_COMMIT();
}

__device__ __forceinline__ void mma_gemm_body(
    const __nv_bfloat16* __restrict__ Ah, const __nv_bfloat16* __restrict__ Al,
    const __nv_bfloat16* __restrict__ Bh, const __nv_bfloat16* __restrict__ Bl,
    float* __restrict__ C, int K, int ldc, int rowA, int rowB, uint32_t sb,
    __nv_bfloat16* __restrict__ Chi, __nv_bfloat16* __restrict__ Clo)
{
    const int tid = threadIdx.x;
    const int wid = tid >> 5;
    const int lane = tid & 31;
    const int wm = wid & 3;
    const int wn = wid >> 2;

    const __nv_bfloat16* src[4] = {Ah, Al, Bh, Bl};

    float accf[2][8][4];
#pragma unroll
    for (int mb = 0; mb < 2; mb++)
#pragma unroll
        for (int nb = 0; nb < 8; nb++)
#pragma unroll
            for (int j = 0; j < 4; j++) accf[mb][nb][j] = 0.f;

    const int KT = K >> 6;
    gemm_fill_stage(sb, src, rowA, rowB, 0, K, tid);
    gemm_fill_stage(sb + GS_STAGE, src, rowA, rowB, 1, K, tid);

    const int aRow = wm * 32 + ((lane >> 3) & 1) * 8 + (lane & 7);
    const int aCol = (lane >> 4);
    const int bRow = wn * 64 + (lane >> 4) * 8 + (lane & 7);
    const int bCol = ((lane >> 3) & 1);

    for (int ck = 0; ck < KT; ck++) {
        if (ck + 2 <= KT) CP_WAIT1(); else CP_WAIT0();
        __syncthreads();
        const uint32_t stage = sb + (ck & 1) * GS_STAGE;

#pragma unroll
        for (int kk = 0; kk < 4; kk++) {
            // load all fragments once: Ah(2), Al(2), Bh(4), Bl(4)
            uint32_t ah[2][4], al_[2][4];
#pragma unroll
            for (int mb = 0; mb < 2; mb++) {
                uint32_t off = SW128((uint32_t)((aRow + mb * 16) * 128 + (aCol + kk * 2) * 16));
                ldsm4(ah[mb],  stage + off);
                ldsm4(al_[mb], stage + GS_ARR + off);
            }
            uint32_t bh_[4][4], bl_[4][4];
#pragma unroll
            for (int nb4 = 0; nb4 < 4; nb4++) {
                uint32_t off = SW128((uint32_t)((bRow + nb4 * 16) * 128 + (bCol + kk * 2) * 16));
                ldsm4(bh_[nb4], stage + 2 * GS_ARR + off);
                ldsm4(bl_[nb4], stage + 3 * GS_ARR + off);
            }
            // 48 MMAs: hh, hl, lh
#pragma unroll
            for (int mb = 0; mb < 2; mb++)
#pragma unroll
                for (int nb = 0; nb < 8; nb++) {
                    const uint32_t* ph = &bh_[nb >> 1][(nb & 1) * 2];
                    const uint32_t* pl = &bl_[nb >> 1][(nb & 1) * 2];
                    mma16816(accf[mb][nb], ah[mb],  ph);
                    mma16816(accf[mb][nb], ah[mb],  pl);
                    mma16816(accf[mb][nb], al_[mb], ph);
                }
        }
        __syncthreads();
        if (ck + 2 < KT)
            gemm_fill_stage(stage, src, rowA, rowB, ck + 2, K, tid);
    }

    const int g = lane >> 2;
    const int t2 = (lane & 3) * 2;
#pragma unroll
    for (int mb = 0; mb < 2; mb++) {
        int r0 = rowA + wm * 32 + mb * 16 + g;
#pragma unroll
        for (int nb = 0; nb < 8; nb++) {
            int col = rowB + wn * 64 + nb * 8 + t2;
            size_t i0 = (size_t)r0 * ldc + col;
            size_t i1 = (size_t)(r0 + 8) * ldc + col;
            C[i0] = accf[mb][nb][0]; C[i0 + 1] = accf[mb][nb][1];
            C[i1] = accf[mb][nb][2]; C[i1 + 1] = accf[mb][nb][3];
            if (Chi) {
                store_split2(Chi, Clo, i0, accf[mb][nb][0], accf[mb][nb][1]);
                store_split2(Chi, Clo, i1, accf[mb][nb][2], accf[mb][nb][3]);
            }
        }
    }
}

__global__ __launch_bounds__(256, 1)
void mma_gemm(const __nv_bfloat16* __restrict__ Ah, const __nv_bfloat16* __restrict__ Al,
              const __nv_bfloat16* __restrict__ Bh, const __nv_bfloat16* __restrict__ Bl,
              float* __restrict__ C, int K, int ldc) {
    extern __shared__ char smc[];
    mma_gemm_body(Ah, Al, Bh, Bl, C, K, ldc,
                  blockIdx.y * 128, blockIdx.x * 128, smem_u32(smc), nullptr, nullptr);
}

// fused K/V projection; V blocks also emit bf16 hi/lo for the flash stage
__global__ __launch_bounds__(256, 1)
void mma_gemm_kv(const __nv_bfloat16* __restrict__ xh, const __nv_bfloat16* __restrict__ xl,
                 const __nv_bfloat16* __restrict__ wkh, const __nv_bfloat16* __restrict__ wkl,
                 const __nv_bfloat16* __restrict__ wvh, const __nv_bfloat16* __restrict__ wvl,
                 float* __restrict__ Ck, float* __restrict__ Cv,
                 __nv_bfloat16* __restrict__ vh, __nv_bfloat16* __restrict__ vl) {
    extern __shared__ char smc[];
    int nb = blockIdx.x;
    const __nv_bfloat16 *bh, *bl;
    float* C;
    __nv_bfloat16 *Chi = nullptr, *Clo = nullptr;
    if (nb < 4) { bh = wkh; bl = wkl; C = Ck; }
    else        { bh = wvh; bl = wvl; C = Cv; Chi = vh; Clo = vl; nb -= 4; }
    mma_gemm_body(xh, xl, bh, bl, C, DIMn, KVD,
                  blockIdx.y * 128, nb * 128, smem_u32(smc), Chi, Clo);
}

// ------- fused RMSNorm + RoPE (+ gain/scale) -> bf16 hi/lo outputs --------
__global__ void normrope_split_kernel(const float* __restrict__ X, int heads,
                                      const float* __restrict__ gain, int use_gain,
                                      float scale,
                                      __nv_bfloat16* __restrict__ oh,
                                      __nv_bfloat16* __restrict__ ol) {
    const int row = blockIdx.x;
    const int h = blockIdx.y;
    const int d = threadIdx.x;
    const int ld = heads * DD;
    const float* p = X + (size_t)row * ld + h * DD;

    float v = p[d];
    __shared__ float sh[DD];
    __shared__ float red[4];
    float sq = v * v;
#pragma unroll
    for (int o = 16; o; o >>= 1) sq += __shfl_xor_sync(0xffffffffu, sq, o);
    if ((d & 31) == 0) red[d >> 5] = sq;
    __syncthreads();
    float tot = red[0] + red[1] + red[2] + red[3];
    float r = rsqrtf(tot * (1.0f / DD) + 1.1920929e-7f);
    sh[d] = v * r;
    __syncthreads();
    if (d < HALF) {
        int t = row & (TT - 1);
        float c = g_cos[t * HALF + d];
        float s = g_sin[t * HALF + d];
        float x1 = sh[d], x2 = sh[d + HALF];
        float gg = (use_gain ? gain[h] : 1.0f) * scale;
        float o1 = (x1 * c + x2 * s) * gg;
        float o2 = (-x1 * s + x2 * c) * gg;
        size_t base = (size_t)row * ld + h * DD + d;
        __nv_bfloat16 h1 = __float2bfloat16(o1);
        __nv_bfloat16 h2 = __float2bfloat16(o2);
        oh[base]        = h1;
        oh[base + HALF] = h2;
        ol[base]        = __float2bfloat16(o1 - __bfloat162float(h1));
        ol[base + HALF] = __float2bfloat16(o2 - __bfloat162float(h2));
    }
}

// ---------------- HMMA flash attention (causal, GQA) ----------------------
// BM=128 (8 warps x 16 rows), BN=64. bf16 hi/lo split operands.
// S: fragment-reuse (Qh,Ql,Kh,Kl loaded once per kk/half -> 10 ldsm / 24 MMA).
// PV: 3 passes (PhVh, PhVl, PlVh). Epilogue writes bf16 hi/lo Y directly.
#define FL_BM 128
#define FL_BN 64
#define FQ_ARR  16384
#define FKV_ARR 8192
#define FKV_OFF 65536
#define FKV_STAGE 65536
#define FLM_SMEM (FKV_OFF + 2 * FKV_STAGE)

__global__ __launch_bounds__(256, 1)
void flash_mma_kernel(const __nv_bfloat16* __restrict__ Qh, const __nv_bfloat16* __restrict__ Ql,
                      const __nv_bfloat16* __restrict__ Kh, const __nv_bfloat16* __restrict__ Kl,
                      const __nv_bfloat16* __restrict__ Vh, const __nv_bfloat16* __restrict__ Vl,
                      __nv_bfloat16* __restrict__ Yh, __nv_bfloat16* __restrict__ Yl) {
    extern __shared__ char smc[];
    const uint32_t sb = smem_u32(smc);
    const int qb = (gridDim.x - 1) - blockIdx.x;   // big tiles first
    const int bh = blockIdx.y;
    const int b = bh / HH, h = bh % HH, kh = h / GG;
    const int q0 = qb * FL_BM;
    const int tid = threadIdx.x;
    const int wid = tid >> 5, lane = tid & 31;

    const __nv_bfloat16* kvsrc[8];
    {
        size_t koff = (size_t)(b * TT) * KVD + kh * DD;
        kvsrc[0] = Kh + koff; kvsrc[1] = Kh + koff + 64;
        kvsrc[2] = Kl + koff; kvsrc[3] = Kl + koff + 64;
        kvsrc[4] = Vh + koff; kvsrc[5] = Vh + koff + 64;
        kvsrc[6] = Vl + koff; kvsrc[7] = Vl + koff + 64;
    }
    auto fill_kv = [&](int blk, int s) {
#pragma unroll
        for (int it = 0; it < 16; it++) {
            int idx = tid + it * 256;
            int arr = idx >> 9, r = (idx >> 3) & 63, p = idx & 7;
            cpa16(sb + FKV_OFF + s * FKV_STAGE + arr * FKV_ARR +
                      SW128((uint32_t)(r * 128 + p * 16)),
                  kvsrc[arr] + (size_t)(blk * FL_BN + r) * KVD + p * 8);
        }
        CP_COMMIT();
    };

    {
        const __nv_bfloat16* qsrc[4];
        size_t qoff = (size_t)(b * TT + q0) * DIMn + h * DD;
        qsrc[0] = Qh + qoff; qsrc[1] = Qh + qoff + 64;
        qsrc[2] = Ql + qoff; qsrc[3] = Ql + qoff + 64;
#pragma unroll
        for (int it = 0; it < 16; it++) {
            int idx = tid + it * 256;
            int arr = idx >> 10, r = (idx >> 3) & 127, p = idx & 7;
            cpa16(sb + arr * FQ_ARR + SW128((uint32_t)(r * 128 + p * 16)),
                  qsrc[arr] + (size_t)r * DIMn + p * 8);
        }
    }
    const int nkb = 2 * qb + 2;
    fill_kv(0, 0);
    if (nkb > 1) fill_kv(1, 1);

    const int aRowOff = ((lane >> 3) & 1) * 8 + (lane & 7);
    const int aPiece  = lane >> 4;
    const int bRowOff = (lane >> 4) * 8 + (lane & 7);
    const int bPiece  = (lane >> 3) & 1;
    const int vRowOff = ((lane >> 3) & 1) * 8 + (lane & 7);
    const int vPiece  = lane >> 4;

    float m0 = -INFINITY, m1 = -INFINITY, l0 = 0.f, l1 = 0.f;
    float oacc[16][4];
#pragma unroll
    for (int i = 0; i < 16; i++)
#pragma unroll
        for (int j = 0; j < 4; j++) oacc[i][j] = 0.f;

    for (int kb = 0; kb < nkb; kb++) {
        if (kb + 1 < nkb) CP_WAIT1(); else CP_WAIT0();
        __syncthreads();
        const uint32_t kvb = sb + FKV_OFF + (kb & 1) * FKV_STAGE;

        // ---- S = Q K^T with fragment reuse ----
        float sacc[8][4];
#pragma unroll
        for (int i = 0; i < 8; i++)
#pragma unroll
            for (int j = 0; j < 4; j++) sacc[i][j] = 0.f;

#pragma unroll
        for (int half = 0; half < 2; half++) {
            const uint32_t qaH = sb + half * FQ_ARR;
            const uint32_t qaL = sb + (2 + half) * FQ_ARR;
            const uint32_t kaH = kvb + half * FKV_ARR;
            const uint32_t kaL = kvb + (2 + half) * FKV_ARR;
#pragma unroll
            for (int kk = 0; kk < 4; kk++) {
                uint32_t aoff = SW128((uint32_t)((wid * 16 + aRowOff) * 128 +
                                                 (aPiece + kk * 2) * 16));
                uint32_t aH[4], aL[4];
                ldsm4(aH, qaH + aoff);
                ldsm4(aL, qaL + aoff);
#pragma unroll
                for (int nt = 0; nt < 4; nt++) {
                    uint32_t boff = SW128((uint32_t)((nt * 16 + bRowOff) * 128 +
                                                     (bPiece + kk * 2) * 16));
                    uint32_t bH[4], bL[4];
                    ldsm4(bH, kaH + boff);
                    ldsm4(bL, kaL + boff);
                    mma16816(sacc[nt * 2],     aH, bH);
                    mma16816(sacc[nt * 2 + 1], aH, bH + 2);
                    mma16816(sacc[nt * 2],     aH, bL);
                    mma16816(sacc[nt * 2 + 1], aH, bL + 2);
                    mma16816(sacc[nt * 2],     aL, bH);
                    mma16816(sacc[nt * 2 + 1], aL, bH + 2);
                }
            }
        }

        // ---- causal mask ----
        const int k0 = kb * FL_BN;
        const int row0 = q0 + wid * 16 + (lane >> 2);
        if (kb >= 2 * qb) {
#pragma unroll
            for (int nt = 0; nt < 8; nt++) {
                int c = k0 + nt * 8 + (lane & 3) * 2;
                if (c > row0)         sacc[nt][0] = -INFINITY;
                if (c + 1 > row0)     sacc[nt][1] = -INFINITY;
                if (c > row0 + 8)     sacc[nt][2] = -INFINITY;
                if (c + 1 > row0 + 8) sacc[nt][3] = -INFINITY;
            }
        }

        // ---- online softmax (exp2 domain) ----
        float mx0 = sacc[0][0], mx1 = sacc[0][2];
#pragma unroll
        for (int nt = 0; nt < 8; nt++) {
            mx0 = fmaxf(mx0, fmaxf(sacc[nt][0], sacc[nt][1]));
            mx1 = fmaxf(mx1, fmaxf(sacc[nt][2], sacc[nt][3]));
        }
        mx0 = fmaxf(mx0, __shfl_xor_sync(0xffffffffu, mx0, 1));
        mx0 = fmaxf(mx0, __shfl_xor_sync(0xffffffffu, mx0, 2));
        mx1 = fmaxf(mx1, __shfl_xor_sync(0xffffffffu, mx1, 1));
        mx1 = fmaxf(mx1, __shfl_xor_sync(0xffffffffu, mx1, 2));
        float mn0 = fmaxf(m0, mx0), mn1 = fmaxf(m1, mx1);
        float al0 = ex2(m0 - mn0), al1 = ex2(m1 - mn1);
        m0 = mn0; m1 = mn1;
        float s0 = 0.f, s1 = 0.f;
#pragma unroll
        for (int nt = 0; nt < 8; nt++) {
            float p0 = ex2(sacc[nt][0] - mn0); sacc[nt][0] = p0; s0 += p0;
            float p1 = ex2(sacc[nt][1] - mn0); sacc[nt][1] = p1; s0 += p1;
            float p2 = ex2(sacc[nt][2] - mn1); sacc[nt][2] = p2; s1 += p2;
            float p3 = ex2(sacc[nt][3] - mn1); sacc[nt][3] = p3; s1 += p3;
        }
        s0 += __shfl_xor_sync(0xffffffffu, s0, 1);
        s0 += __shfl_xor_sync(0xffffffffu, s0, 2);
        s1 += __shfl_xor_sync(0xffffffffu, s1, 1);
        s1 += __shfl_xor_sync(0xffffffffu, s1, 2);
        l0 = l0 * al0 + s0;
        l1 = l1 * al1 + s1;
#pragma unroll
        for (int ot = 0; ot < 16; ot++) {
            oacc[ot][0] *= al0; oacc[ot][1] *= al0;
            oacc[ot][2] *= al1; oacc[ot][3] *= al1;
        }

        // ---- O += P V (3 split passes) ----
#pragma unroll
        for (int kk = 0; kk < 4; kk++) {
            uint32_t pha[4], pla[4];
            split_pack2(sacc[2 * kk][0],     sacc[2 * kk][1],     pha[0], pla[0]);
            split_pack2(sacc[2 * kk][2],     sacc[2 * kk][3],     pha[1], pla[1]);
            split_pack2(sacc[2 * kk + 1][0], sacc[2 * kk + 1][1], pha[2], pla[2]);
            split_pack2(sacc[2 * kk + 1][2], sacc[2 * kk + 1][3], pha[3], pla[3]);
#pragma unroll
            for (int half = 0; half < 2; half++) {
                const uint32_t vha = kvb + (4 + half) * FKV_ARR;
                const uint32_t vla = kvb + (6 + half) * FKV_ARR;
#pragma unroll
                for (int dt = 0; dt < 4; dt++) {
                    uint32_t aoff = SW128((uint32_t)((kk * 16 + vRowOff) * 128 +
                                                     (dt * 2 + vPiece) * 16));
                    uint32_t bh_[4], bl_[4];
                    ldsm4t(bh_, vha + aoff);
                    ldsm4t(bl_, vla + aoff);
                    const int ot = half * 8 + dt * 2;
                    mma16816(oacc[ot],     pha, bh_);
                    mma16816(oacc[ot + 1], pha, bh_ + 2);
                    mma16816(oacc[ot],     pha, bl_);
                    mma16816(oacc[ot + 1], pha, bl_ + 2);
                    mma16816(oacc[ot],     pla, bh_);
                    mma16816(oacc[ot + 1], pla, bh_ + 2);
                }
            }
        }

        __syncthreads();
        if (kb + 2 < nkb) fill_kv(kb + 2, kb & 1);
    }

    // ---- epilogue: write bf16 hi/lo Y directly ----
    const float inv0 = 1.f / l0, inv1 = 1.f / l1;
    const int rg = b * TT + q0 + wid * 16 + (lane >> 2);
    const size_t base0 = (size_t)rg * DIMn + h * DD + (lane & 3) * 2;
    const size_t base1 = base0 + (size_t)8 * DIMn;
#pragma unroll
    for (int ot = 0; ot < 16; ot++) {
        int d = (ot >> 3) * 64 + ((ot >> 1) & 3) * 16 + (ot & 1) * 8;
        store_split2(Yh, Yl, base0 + d, oacc[ot][0] * inv0, oacc[ot][1] * inv0);
        store_split2(Yh, Yl, base1 + d, oacc[ot][2] * inv1, oacc[ot][3] * inv1);
    }
}

// ---------------- host launcher ----------------
extern "C" void kernel_launch(void* const* d_in, const int* in_sizes, int n_in,
                              void* d_out, int out_size) {
    const float* x     = (const float*)d_in[0];
    const float* Wq    = (const float*)d_in[1];
    const float* Wk    = (const float*)d_in[2];
    const float* Wv    = (const float*)d_in[3];
    const float* Wproj = (const float*)d_in[4];
    const float* qgain = (const float*)d_in[5];
    float* out = (float*)d_out;

    float *q_ptr, *k_ptr;
    cudaGetSymbolAddress((void**)&q_ptr, g_Q);
    cudaGetSymbolAddress((void**)&k_ptr, g_K);
    __nv_bfloat16 *xh, *xl, *wqh, *wql, *wkh, *wkl, *wvh, *wvl, *wph, *wpl, *yh, *yl;
    __nv_bfloat16 *qh2, *ql2, *kh2, *kl2, *vh2, *vl2;
    cudaGetSymbolAddress((void**)&xh, g_xh);   cudaGetSymbolAddress((void**)&xl, g_xl);
    cudaGetSymbolAddress((void**)&wqh, g_wqh); cudaGetSymbolAddress((void**)&wql, g_wql);
    cudaGetSymbolAddress((void**)&wkh, g_wkh); cudaGetSymbolAddress((void**)&wkl, g_wkl);
    cudaGetSymbolAddress((void**)&wvh, g_wvh); cudaGetSymbolAddress((void**)&wvl, g_wvl);
    cudaGetSymbolAddress((void**)&wph, g_wph); cudaGetSymbolAddress((void**)&wpl, g_wpl);
    cudaGetSymbolAddress((void**)&yh, g_yh);   cudaGetSymbolAddress((void**)&yl, g_yl);
    cudaGetSymbolAddress((void**)&qh2, g_qh2); cudaGetSymbolAddress((void**)&ql2, g_ql2);
    cudaGetSymbolAddress((void**)&kh2, g_kh2); cudaGetSymbolAddress((void**)&kl2, g_kl2);
    cudaGetSymbolAddress((void**)&vh2, g_vh2); cudaGetSymbolAddress((void**)&vl2, g_vl2);

    float* v_out = out + (size_t)NTOK * DIMn;   // v is the second output

    cudaFuncSetAttribute(mma_gemm, cudaFuncAttributeMaxDynamicSharedMemorySize, GEMM_SMEM);
    cudaFuncSetAttribute(mma_gemm_kv, cudaFuncAttributeMaxDynamicSharedMemorySize, GEMM_SMEM);
    cudaFuncSetAttribute(flash_mma_kernel, cudaFuncAttributeMaxDynamicSharedMemorySize, FLM_SMEM);

    const float qscale = 0.08838834764831845f * 1.4426950408889634f;  // 1/sqrt(D)*log2(e)

    // 1. RoPE tables + input/weight splits
    rope_table_kernel<<<(TT * HALF + 255) / 256, 256>>>();
    split_kernel<<<(NTOK * DIMn / 4 + 255) / 256, 256>>>(x, xh, xl, NTOK * DIMn / 4);
    split_kernel<<<(DIMn * DIMn / 4 + 255) / 256, 256>>>(Wq, wqh, wql, DIMn * DIMn / 4);
    split_kernel<<<(KVD * DIMn / 4 + 255) / 256, 256>>>(Wk, wkh, wkl, KVD * DIMn / 4);
    split_kernel<<<(KVD * DIMn / 4 + 255) / 256, 256>>>(Wv, wvh, wvl, KVD * DIMn / 4);
    split_kernel<<<(DIMn * DIMn / 4 + 255) / 256, 256>>>(Wproj, wph, wpl, DIMn * DIMn / 4);

    // 2. QKV projections (V -> output tail fp32 + bf16 hi/lo fused)
    mma_gemm<<<dim3(DIMn / 128, NTOK / 128), 256, GEMM_SMEM>>>(xh, xl, wqh, wql, q_ptr, DIMn, DIMn);
    mma_gemm_kv<<<dim3(8, NTOK / 128), 256, GEMM_SMEM>>>(xh, xl, wkh, wkl, wvh, wvl,
                                                         k_ptr, v_out, vh2, vl2);

    // 3. RMSNorm + RoPE -> bf16 hi/lo directly (q: gain + attention scale)
    normrope_split_kernel<<<dim3(NTOK, HH), 128>>>(q_ptr, HH, qgain, 1, qscale, qh2, ql2);
    normrope_split_kernel<<<dim3(NTOK, HKVn), 128>>>(k_ptr, HKVn, nullptr, 0, 1.0f, kh2, kl2);

    // 4. causal GQA flash attention on HMMA -> bf16 hi/lo Y
    flash_mma_kernel<<<dim3(TT / FL_BM, BB * HH), 256, FLM_SMEM>>>(
        qh2, ql2, kh2, kl2, vh2, vl2, yh, yl);

    // 5. output projection on HMMA
    mma_gemm<<<dim3(DIMn / 128, NTOK / 128), 256, GEMM_SMEM>>>(yh, yl, wph, wpl, out, DIMn, DIMn);
}

// round 16
// speedup vs baseline: 7.5338x; 1.2304x over previous
#include <cuda_runtime.h>
#include <cuda_bf16.h>
#include <cuda_fp16.h>
#include <math.h>
#include <stdint.h>

// ---------------- problem constants ----------------
#define BB   2
#define TT   2048
#define HH   16
#define HKVn 4
#define DD   128
#define GG   4
#define DIMn 2048           // HH*DD
#define KVD  512            // HKVn*DD
#define NTOK (BB*TT)        // 4096
#define HALF 64             // DD/2

#define WSCALE 4096.0f      // weight pre-scale (keeps fp16 residuals normal)
#define CINV   (1.0f / 4096.0f)

// ---------------- device scratch (no allocs allowed) ----------------
__device__ float g_Q[(size_t)NTOK * DIMn];     // fp32 Q proj (pre-norm)
__device__ float g_K[(size_t)NTOK * KVD];      // fp32 K proj (pre-norm)
__device__ float g_cos[TT * HALF];
__device__ float g_sin[TT * HALF];
// fp16 GEMM operands (A-side hi only; B-side hi+lo, pre-scaled by WSCALE)
__device__ __align__(16) __half g_x16[(size_t)NTOK * DIMn];
__device__ __align__(16) __half g_wq16h[(size_t)DIMn * DIMn], g_wq16l[(size_t)DIMn * DIMn];
__device__ __align__(16) __half g_wk16h[(size_t)KVD * DIMn],  g_wk16l[(size_t)KVD * DIMn];
__device__ __align__(16) __half g_wv16h[(size_t)KVD * DIMn],  g_wv16l[(size_t)KVD * DIMn];
__device__ __align__(16) __half g_wp16h[(size_t)DIMn * DIMn], g_wp16l[(size_t)DIMn * DIMn];
__device__ __align__(16) __half g_y16[(size_t)NTOK * DIMn];
// flash operands (normed Q/K, V) split bf16 hi/lo (3-pass flash unchanged)
__device__ __align__(16) __nv_bfloat16 g_qh2[(size_t)NTOK * DIMn], g_ql2[(size_t)NTOK * DIMn];
__device__ __align__(16) __nv_bfloat16 g_kh2[(size_t)NTOK * KVD],  g_kl2[(size_t)NTOK * KVD];
__device__ __align__(16) __nv_bfloat16 g_vh2[(size_t)NTOK * KVD],  g_vl2[(size_t)NTOK * KVD];

// ---------------- PTX helpers (portable, no arch-specific features) -------
__device__ __forceinline__ uint32_t smem_u32(const void* p) {
    uint32_t a;
    asm("{ .reg .u64 t; cvta.to.shared.u64 t, %1; cvt.u32.u64 %0, t; }" : "=r"(a) : "l"(p));
    return a;
}
__device__ __forceinline__ float ex2(float x) {
    float r; asm("ex2.approx.ftz.f32 %0, %1;" : "=f"(r) : "f"(x)); return r;
}
__device__ __forceinline__ void cpa16(uint32_t dst_smem, const void* src_gmem) {
    asm volatile("cp.async.cg.shared.global [%0], [%1], 16;" :: "r"(dst_smem), "l"(src_gmem));
}
#define CP_COMMIT()  asm volatile("cp.async.commit_group;" ::: "memory")
#define CP_WAIT0()   asm volatile("cp.async.wait_group 0;" ::: "memory")
#define CP_WAIT1()   asm volatile("cp.async.wait_group 1;" ::: "memory")

__device__ __forceinline__ void ldsm4(uint32_t* r, uint32_t addr) {
    asm volatile("ldmatrix.sync.aligned.m8n8.x4.shared.b16 {%0,%1,%2,%3}, [%4];"
        : "=r"(r[0]), "=r"(r[1]), "=r"(r[2]), "=r"(r[3]) : "r"(addr));
}
__device__ __forceinline__ void ldsm4t(uint32_t* r, uint32_t addr) {
    asm volatile("ldmatrix.sync.aligned.m8n8.x4.trans.shared.b16 {%0,%1,%2,%3}, [%4];"
        : "=r"(r[0]), "=r"(r[1]), "=r"(r[2]), "=r"(r[3]) : "r"(addr));
}
// bf16 MMA (flash)
__device__ __forceinline__ void mma16816(float* d, const uint32_t* a, const uint32_t* b) {
    asm volatile("mma.sync.aligned.m16n8k16.row.col.f32.bf16.bf16.f32 "
        "{%0,%1,%2,%3}, {%4,%5,%6,%7}, {%8,%9}, {%0,%1,%2,%3};"
        : "+f"(d[0]), "+f"(d[1]), "+f"(d[2]), "+f"(d[3])
        : "r"(a[0]), "r"(a[1]), "r"(a[2]), "r"(a[3]), "r"(b[0]), "r"(b[1]));
}
// fp16 MMA (projection GEMMs)
__device__ __forceinline__ void mma16816h(float* d, const uint32_t* a, const uint32_t* b) {
    asm volatile("mma.sync.aligned.m16n8k16.row.col.f32.f16.f16.f32 "
        "{%0,%1,%2,%3}, {%4,%5,%6,%7}, {%8,%9}, {%0,%1,%2,%3};"
        : "+f"(d[0]), "+f"(d[1]), "+f"(d[2]), "+f"(d[3])
        : "r"(a[0]), "r"(a[1]), "r"(a[2]), "r"(a[3]), "r"(b[0]), "r"(b[1]));
}
// pack two fp32 into one bf16x2 reg and its residual (flash P split)
__device__ __forceinline__ void split_pack2(float x, float y, uint32_t& hi, uint32_t& lo) {
    __nv_bfloat16 hx = __float2bfloat16(x), hy = __float2bfloat16(y);
    float lx = x - __bfloat162float(hx), ly = y - __bfloat162float(hy);
    __nv_bfloat162 hv(hx, hy);
    __nv_bfloat162 lv(__float2bfloat16(lx), __float2bfloat16(ly));
    hi = *reinterpret_cast<uint32_t*>(&hv);
    lo = *reinterpret_cast<uint32_t*>(&lv);
}
__device__ __forceinline__ void store_split2(__nv_bfloat16* H, __nv_bfloat16* L,
                                             size_t idx, float x, float y) {
    uint32_t hi, lo;
    split_pack2(x, y, hi, lo);
    *(uint32_t*)(H + idx) = hi;
    *(uint32_t*)(L + idx) = lo;
}

#define SW128(off) ((off) ^ (((off) >> 3) & 0x70))

// ---------------- RoPE table (NTK-scaled, T > train_seq_len) --------------
__global__ void rope_table_kernel() {
    int idx = blockIdx.x * blockDim.x + threadIdx.x;
    if (idx >= TT * HALF) return;
    int t = idx >> 6;
    int i = idx & 63;
    double base = 10000.0 * pow(2.0, 128.0 / 126.0);
    double inv  = pow(base, -((double)(2 * i)) / 128.0);
    double ang  = (double)t * inv;
    g_cos[idx] = (float)cos(ang);
    g_sin[idx] = (float)sin(ang);
}

// ---------------- fp32 -> fp16 splits --------------------------------------
__global__ void split_hi_f16(const float* __restrict__ x, __half* __restrict__ hi, int n4) {
    int i = blockIdx.x * blockDim.x + threadIdx.x;
    if (i >= n4) return;
    float4 v = ((const float4*)x)[i];
    ((__half2*)hi)[2 * i]     = __floats2half2_rn(v.x, v.y);
    ((__half2*)hi)[2 * i + 1] = __floats2half2_rn(v.z, v.w);
}
__global__ void split_hilo_f16(const float* __restrict__ x,
                               __half* __restrict__ hi, __half* __restrict__ lo, int n4) {
    int i = blockIdx.x * blockDim.x + threadIdx.x;
    if (i >= n4) return;
    float4 v = ((const float4*)x)[i];
    float a0 = v.x * WSCALE, a1 = v.y * WSCALE, a2 = v.z * WSCALE, a3 = v.w * WSCALE;
    __half h0 = __float2half_rn(a0), h1 = __float2half_rn(a1);
    __half h2 = __float2half_rn(a2), h3 = __float2half_rn(a3);
    ((__half2*)hi)[2 * i]     = __half2(h0, h1);
    ((__half2*)hi)[2 * i + 1] = __half2(h2, h3);
    ((__half2*)lo)[2 * i]     = __floats2half2_rn(a0 - __half2float(h0), a1 - __half2float(h1));
    ((__half2*)lo)[2 * i + 1] = __floats2half2_rn(a2 - __half2float(h2), a3 - __half2float(h3));
}

// ---------------- fp16 2-pass GEMM on mma.sync (HMMA) ---------------------
// C = A*(Bh+Bl)^T * CINV, A fp16-hi-only, B pre-scaled by WSCALE.
// smem: 2 stages x {A, Bh, Bl} x 16KB = 96KB -> 2 CTAs/SM.
#define GS_ARR    16384
#define GS_STAGE  (3 * GS_ARR)
#define GEMM_SMEM (2 * GS_STAGE)

__device__ __forceinline__ void gemm_fill_stage2(
    uint32_t stage, const __half* __restrict__ A,
    const __half* __restrict__ Bh, const __half* __restrict__ Bl,
    int rowA, int rowB, int ck, int K, int tid)
{
    const __half* src[3] = {A, Bh, Bl};
#pragma unroll
    for (int it = 0; it < 12; it++) {
        int idx = tid + it * 256;              // 0..3071
        int arr = idx >> 10;                   // 0..2
        int r   = (idx >> 3) & 127;
        int p   = idx & 7;
        uint32_t off = SW128((uint32_t)(r * 128 + p * 16));
        int grow = ((arr == 0) ? rowA : rowB) + r;
        cpa16(stage + arr * GS_ARR + off, src[arr] + (size_t)grow * K + ck * 64 + p * 8);
    }
    CP_COMMIT();
}

__device__ __forceinline__ void mma_gemm_body2(
    const __half* __restrict__ A,
    const __half* __restrict__ Bh, const __half* __restrict__ Bl,
    float* __restrict__ C, int K, int ldc, int rowA, int rowB, uint32_t sb,
    __nv_bfloat16* __restrict__ Chi, __nv_bfloat16* __restrict__ Clo)
{
    const int tid = threadIdx.x;
    const int wid = tid >> 5;
    const int lane = tid & 31;
    const int wm = wid & 3;
    const int wn = wid >> 2;

    float accf[2][8][4];
#pragma unroll
    for (int mb = 0; mb < 2; mb++)
#pragma unroll
        for (int nb = 0; nb < 8; nb++)
#pragma unroll
            for (int j = 0; j < 4; j++) accf[mb][nb][j] = 0.f;

    const int KT = K >> 6;
    gemm_fill_stage2(sb, A, Bh, Bl, rowA, rowB, 0, K, tid);
    gemm_fill_stage2(sb + GS_STAGE, A, Bh, Bl, rowA, rowB, 1, K, tid);

    const int aRow = wm * 32 + ((lane >> 3) & 1) * 8 + (lane & 7);
    const int aCol = (lane >> 4);
    const int bRow = wn * 64 + (lane >> 4) * 8 + (lane & 7);
    const int bCol = ((lane >> 3) & 1);

    for (int ck = 0; ck < KT; ck++) {
        if (ck + 2 <= KT) CP_WAIT1(); else CP_WAIT0();
        __syncthreads();
        const uint32_t stage = sb + (ck & 1) * GS_STAGE;

#pragma unroll
        for (int kk = 0; kk < 4; kk++) {
            uint32_t ah[2][4];
#pragma unroll
            for (int mb = 0; mb < 2; mb++) {
                uint32_t off = SW128((uint32_t)((aRow + mb * 16) * 128 + (aCol + kk * 2) * 16));
                ldsm4(ah[mb], stage + off);
            }
            uint32_t bh_[4][4], bl_[4][4];
#pragma unroll
            for (int nb4 = 0; nb4 < 4; nb4++) {
                uint32_t off = SW128((uint32_t)((bRow + nb4 * 16) * 128 + (bCol + kk * 2) * 16));
                ldsm4(bh_[nb4], stage + GS_ARR + off);
                ldsm4(bl_[nb4], stage + 2 * GS_ARR + off);
            }
#pragma unroll
            for (int mb = 0; mb < 2; mb++)
#pragma unroll
                for (int nb = 0; nb < 8; nb++) {
                    mma16816h(accf[mb][nb], ah[mb], &bh_[nb >> 1][(nb & 1) * 2]);
                    mma16816h(accf[mb][nb], ah[mb], &bl_[nb >> 1][(nb & 1) * 2]);
                }
        }
        __syncthreads();
        if (ck + 2 < KT)
            gemm_fill_stage2(stage, A, Bh, Bl, rowA, rowB, ck + 2, K, tid);
    }

    const int g = lane >> 2;
    const int t2 = (lane & 3) * 2;
#pragma unroll
    for (int mb = 0; mb < 2; mb++) {
        int r0 = rowA + wm * 32 + mb * 16 + g;
#pragma unroll
        for (int nb = 0; nb < 8; nb++) {
            int col = rowB + wn * 64 + nb * 8 + t2;
            size_t i0 = (size_t)r0 * ldc + col;
            size_t i1 = (size_t)(r0 + 8) * ldc + col;
            float v00 = accf[mb][nb][0] * CINV, v01 = accf[mb][nb][1] * CINV;
            float v10 = accf[mb][nb][2] * CINV, v11 = accf[mb][nb][3] * CINV;
            C[i0] = v00; C[i0 + 1] = v01;
            C[i1] = v10; C[i1 + 1] = v11;
            if (Chi) {
                store_split2(Chi, Clo, i0, v00, v01);
                store_split2(Chi, Clo, i1, v10, v11);
            }
        }
    }
}

// fused Q + K + V projections in a single launch: grid (24, 32)
__global__ __launch_bounds__(256, 2)
void mma_gemm_qkv(const __half* __restrict__ x16,
                  const __half* __restrict__ wqh, const __half* __restrict__ wql,
                  const __half* __restrict__ wkh, const __half* __restrict__ wkl,
                  const __half* __restrict__ wvh, const __half* __restrict__ wvl,
                  float* __restrict__ Cq, float* __restrict__ Ck, float* __restrict__ Cv,
                  __nv_bfloat16* __restrict__ vh, __nv_bfloat16* __restrict__ vl) {
    extern __shared__ char smc[];
    const uint32_t sb = smem_u32(smc);
    const int bx = blockIdx.x;
    const int rowA = blockIdx.y * 128;
    if (bx < 16) {
        mma_gemm_body2(x16, wqh, wql, Cq, DIMn, DIMn, rowA, bx * 128, sb, nullptr, nullptr);
    } else if (bx < 20) {
        mma_gemm_body2(x16, wkh, wkl, Ck, DIMn, KVD, rowA, (bx - 16) * 128, sb, nullptr, nullptr);
    } else {
        mma_gemm_body2(x16, wvh, wvl, Cv, DIMn, KVD, rowA, (bx - 20) * 128, sb, vh, vl);
    }
}

__global__ __launch_bounds__(256, 2)
void mma_gemm_proj(const __half* __restrict__ A,
                   const __half* __restrict__ Bh, const __half* __restrict__ Bl,
                   float* __restrict__ C) {
    extern __shared__ char smc[];
    mma_gemm_body2(A, Bh, Bl, C, DIMn, DIMn,
                   blockIdx.y * 128, blockIdx.x * 128, smem_u32(smc), nullptr, nullptr);
}

// ------- fused RMSNorm + RoPE (+ gain/scale) -> bf16 hi/lo outputs --------
__global__ void normrope_split_kernel(const float* __restrict__ X, int heads,
                                      const float* __restrict__ gain, int use_gain,
                                      float scale,
                                      __nv_bfloat16* __restrict__ oh,
                                      __nv_bfloat16* __restrict__ ol) {
    const int row = blockIdx.x;
    const int h = blockIdx.y;
    const int d = threadIdx.x;
    const int ld = heads * DD;
    const float* p = X + (size_t)row * ld + h * DD;

    float v = p[d];
    __shared__ float sh[DD];
    __shared__ float red[4];
    float sq = v * v;
#pragma unroll
    for (int o = 16; o; o >>= 1) sq += __shfl_xor_sync(0xffffffffu, sq, o);
    if ((d & 31) == 0) red[d >> 5] = sq;
    __syncthreads();
    float tot = red[0] + red[1] + red[2] + red[3];
    float r = rsqrtf(tot * (1.0f / DD) + 1.1920929e-7f);
    sh[d] = v * r;
    __syncthreads();
    if (d < HALF) {
        int t = row & (TT - 1);
        float c = g_cos[t * HALF + d];
        float s = g_sin[t * HALF + d];
        float x1 = sh[d], x2 = sh[d + HALF];
        float gg = (use_gain ? gain[h] : 1.0f) * scale;
        float o1 = (x1 * c + x2 * s) * gg;
        float o2 = (-x1 * s + x2 * c) * gg;
        size_t base = (size_t)row * ld + h * DD + d;
        __nv_bfloat16 h1 = __float2bfloat16(o1);
        __nv_bfloat16 h2 = __float2bfloat16(o2);
        oh[base]        = h1;
        oh[base + HALF] = h2;
        ol[base]        = __float2bfloat16(o1 - __bfloat162float(h1));
        ol[base + HALF] = __float2bfloat16(o2 - __bfloat162float(h2));
    }
}

// ---------------- HMMA flash attention (causal, GQA) ----------------------
// BM=128 (8 warps x 16 rows), BN=64. bf16 hi/lo split operands, 3-pass.
// Epilogue writes fp16-hi Y directly for the fp16 2-pass proj GEMM.
#define FL_BM 128
#define FL_BN 64
#define FQ_ARR  16384
#define FKV_ARR 8192
#define FKV_OFF 65536
#define FKV_STAGE 65536
#define FLM_SMEM (FKV_OFF + 2 * FKV_STAGE)

__global__ __launch_bounds__(256, 1)
void flash_mma_kernel(const __nv_bfloat16* __restrict__ Qh, const __nv_bfloat16* __restrict__ Ql,
                      const __nv_bfloat16* __restrict__ Kh, const __nv_bfloat16* __restrict__ Kl,
                      const __nv_bfloat16* __restrict__ Vh, const __nv_bfloat16* __restrict__ Vl,
                      __half* __restrict__ Y) {
    extern __shared__ char smc[];
    const uint32_t sb = smem_u32(smc);
    const int qb = (gridDim.x - 1) - blockIdx.x;   // big tiles first
    const int bh = blockIdx.y;
    const int b = bh / HH, h = bh % HH, kh = h / GG;
    const int q0 = qb * FL_BM;
    const int tid = threadIdx.x;
    const int wid = tid >> 5, lane = tid & 31;

    const __nv_bfloat16* kvsrc[8];
    {
        size_t koff = (size_t)(b * TT) * KVD + kh * DD;
        kvsrc[0] = Kh + koff; kvsrc[1] = Kh + koff + 64;
        kvsrc[2] = Kl + koff; kvsrc[3] = Kl + koff + 64;
        kvsrc[4] = Vh + koff; kvsrc[5] = Vh + koff + 64;
        kvsrc[6] = Vl + koff; kvsrc[7] = Vl + koff + 64;
    }
    auto fill_kv = [&](int blk, int s) {
#pragma unroll
        for (int it = 0; it < 16; it++) {
            int idx = tid + it * 256;
            int arr = idx >> 9, r = (idx >> 3) & 63, p = idx & 7;
            cpa16(sb + FKV_OFF + s * FKV_STAGE + arr * FKV_ARR +
                      SW128((uint32_t)(r * 128 + p * 16)),
                  kvsrc[arr] + (size_t)(blk * FL_BN + r) * KVD + p * 8);
        }
        CP_COMMIT();
    };

    {
        const __nv_bfloat16* qsrc[4];
        size_t qoff = (size_t)(b * TT + q0) * DIMn + h * DD;
        qsrc[0] = Qh + qoff; qsrc[1] = Qh + qoff + 64;
        qsrc[2] = Ql + qoff; qsrc[3] = Ql + qoff + 64;
#pragma unroll
        for (int it = 0; it < 16; it++) {
            int idx = tid + it * 256;
            int arr = idx >> 10, r = (idx >> 3) & 127, p = idx & 7;
            cpa16(sb + arr * FQ_ARR + SW128((uint32_t)(r * 128 + p * 16)),
                  qsrc[arr] + (size_t)r * DIMn + p * 8);
        }
    }
    const int nkb = 2 * qb + 2;
    fill_kv(0, 0);
    if (nkb > 1) fill_kv(1, 1);

    const int aRowOff = ((lane >> 3) & 1) * 8 + (lane & 7);
    const int aPiece  = lane >> 4;
    const int bRowOff = (lane >> 4) * 8 + (lane & 7);
    const int bPiece  = (lane >> 3) & 1;
    const int vRowOff = ((lane >> 3) & 1) * 8 + (lane & 7);
    const int vPiece  = lane >> 4;

    float m0 = -INFINITY, m1 = -INFINITY, l0 = 0.f, l1 = 0.f;
    float oacc[16][4];
#pragma unroll
    for (int i = 0; i < 16; i++)
#pragma unroll
        for (int j = 0; j < 4; j++) oacc[i][j] = 0.f;

    for (int kb = 0; kb < nkb; kb++) {
        if (kb + 1 < nkb) CP_WAIT1(); else CP_WAIT0();
        __syncthreads();
        const uint32_t kvb = sb + FKV_OFF + (kb & 1) * FKV_STAGE;

        // ---- S = Q K^T with fragment reuse ----
        float sacc[8][4];
#pragma unroll
        for (int i = 0; i < 8; i++)
#pragma unroll
            for (int j = 0; j < 4; j++) sacc[i][j] = 0.f;

#pragma unroll
        for (int half = 0; half < 2; half++) {
            const uint32_t qaH = sb + half * FQ_ARR;
            const uint32_t qaL = sb + (2 + half) * FQ_ARR;
            const uint32_t kaH = kvb + half * FKV_ARR;
            const uint32_t kaL = kvb + (2 + half) * FKV_ARR;
#pragma unroll
            for (int kk = 0; kk < 4; kk++) {
                uint32_t aoff = SW128((uint32_t)((wid * 16 + aRowOff) * 128 +
                                                 (aPiece + kk * 2) * 16));
                uint32_t aH[4], aL[4];
                ldsm4(aH, qaH + aoff);
                ldsm4(aL, qaL + aoff);
#pragma unroll
                for (int nt = 0; nt < 4; nt++) {
                    uint32_t boff = SW128((uint32_t)((nt * 16 + bRowOff) * 128 +
                                                     (bPiece + kk * 2) * 16));
                    uint32_t bH[4], bL[4];
                    ldsm4(bH, kaH + boff);
                    ldsm4(bL, kaL + boff);
                    mma16816(sacc[nt * 2],     aH, bH);
                    mma16816(sacc[nt * 2 + 1], aH, bH + 2);
                    mma16816(sacc[nt * 2],     aH, bL);
                    mma16816(sacc[nt * 2 + 1], aH, bL + 2);
                    mma16816(sacc[nt * 2],     aL, bH);
                    mma16816(sacc[nt * 2 + 1], aL, bH + 2);
                }
            }
        }

        // ---- causal mask ----
        const int k0 = kb * FL_BN;
        const int row0 = q0 + wid * 16 + (lane >> 2);
        if (kb >= 2 * qb) {
#pragma unroll
            for (int nt = 0; nt < 8; nt++) {
                int c = k0 + nt * 8 + (lane & 3) * 2;
                if (c > row0)         sacc[nt][0] = -INFINITY;
                if (c + 1 > row0)     sacc[nt][1] = -INFINITY;
                if (c > row0 + 8)     sacc[nt][2] = -INFINITY;
                if (c + 1 > row0 + 8) sacc[nt][3] = -INFINITY;
            }
        }

        // ---- online softmax (exp2 domain) ----
        float mx0 = sacc[0][0], mx1 = sacc[0][2];
#pragma unroll
        for (int nt = 0; nt < 8; nt++) {
            mx0 = fmaxf(mx0, fmaxf(sacc[nt][0], sacc[nt][1]));
            mx1 = fmaxf(mx1, fmaxf(sacc[nt][2], sacc[nt][3]));
        }
        mx0 = fmaxf(mx0, __shfl_xor_sync(0xffffffffu, mx0, 1));
        mx0 = fmaxf(mx0, __shfl_xor_sync(0xffffffffu, mx0, 2));
        mx1 = fmaxf(mx1, __shfl_xor_sync(0xffffffffu, mx1, 1));
        mx1 = fmaxf(mx1, __shfl_xor_sync(0xffffffffu, mx1, 2));
        float mn0 = fmaxf(m0, mx0), mn1 = fmaxf(m1, mx1);
        float al0 = ex2(m0 - mn0), al1 = ex2(m1 - mn1);
        m0 = mn0; m1 = mn1;
        float s0 = 0.f, s1 = 0.f;
#pragma unroll
        for (int nt = 0; nt < 8; nt++) {
            float p0 = ex2(sacc[nt][0] - mn0); sacc[nt][0] = p0; s0 += p0;
            float p1 = ex2(sacc[nt][1] - mn0); sacc[nt][1] = p1; s0 += p1;
            float p2 = ex2(sacc[nt][2] - mn1); sacc[nt][2] = p2; s1 += p2;
            float p3 = ex2(sacc[nt][3] - mn1); sacc[nt][3] = p3; s1 += p3;
        }
        s0 += __shfl_xor_sync(0xffffffffu, s0, 1);
        s0 += __shfl_xor_sync(0xffffffffu, s0, 2);
        s1 += __shfl_xor_sync(0xffffffffu, s1, 1);
        s1 += __shfl_xor_sync(0xffffffffu, s1, 2);
        l0 = l0 * al0 + s0;
        l1 = l1 * al1 + s1;
#pragma unroll
        for (int ot = 0; ot < 16; ot++) {
            oacc[ot][0] *= al0; oacc[ot][1] *= al0;
            oacc[ot][2] *= al1; oacc[ot][3] *= al1;
        }

        // ---- O += P V (3 split passes) ----
#pragma unroll
        for (int kk = 0; kk < 4; kk++) {
            uint32_t pha[4], pla[4];
            split_pack2(sacc[2 * kk][0],     sacc[2 * kk][1],     pha[0], pla[0]);
            split_pack2(sacc[2 * kk][2],     sacc[2 * kk][3],     pha[1], pla[1]);
            split_pack2(sacc[2 * kk + 1][0], sacc[2 * kk + 1][1], pha[2], pla[2]);
            split_pack2(sacc[2 * kk + 1][2], sacc[2 * kk + 1][3], pha[3], pla[3]);
#pragma unroll
            for (int half = 0; half < 2; half++) {
                const uint32_t vha = kvb + (4 + half) * FKV_ARR;
                const uint32_t vla = kvb + (6 + half) * FKV_ARR;
#pragma unroll
                for (int dt = 0; dt < 4; dt++) {
                    uint32_t aoff = SW128((uint32_t)((kk * 16 + vRowOff) * 128 +
                                                     (dt * 2 + vPiece) * 16));
                    uint32_t bh_[4], bl_[4];
                    ldsm4t(bh_, vha + aoff);
                    ldsm4t(bl_, vla + aoff);
                    const int ot = half * 8 + dt * 2;
                    mma16816(oacc[ot],     pha, bh_);
                    mma16816(oacc[ot + 1], pha, bh_ + 2);
                    mma16816(oacc[ot],     pha, bl_);
                    mma16816(oacc[ot + 1], pha, bl_ + 2);
                    mma16816(oacc[ot],     pla, bh_);
                    mma16816(oacc[ot + 1], pla, bh_ + 2);
                }
            }
        }

        __syncthreads();
        if (kb + 2 < nkb) fill_kv(kb + 2, kb & 1);
    }

    // ---- epilogue: fp16-hi Y for the proj GEMM ----
    const float inv0 = 1.f / l0, inv1 = 1.f / l1;
    const int rg = b * TT + q0 + wid * 16 + (lane >> 2);
    const size_t base0 = (size_t)rg * DIMn + h * DD + (lane & 3) * 2;
    const size_t base1 = base0 + (size_t)8 * DIMn;
#pragma unroll
    for (int ot = 0; ot < 16; ot++) {
        int d = (ot >> 3) * 64 + ((ot >> 1) & 3) * 16 + (ot & 1) * 8;
        *(__half2*)(Y + base0 + d) = __floats2half2_rn(oacc[ot][0] * inv0, oacc[ot][1] * inv0);
        *(__half2*)(Y + base1 + d) = __floats2half2_rn(oacc[ot][2] * inv1, oacc[ot][3] * inv1);
    }
}

// ---------------- host launcher ----------------
extern "C" void kernel_launch(void* const* d_in, const int* in_sizes, int n_in,
                              void* d_out, int out_size) {
    const float* x     = (const float*)d_in[0];
    const float* Wq    = (const float*)d_in[1];
    const float* Wk    = (const float*)d_in[2];
    const float* Wv    = (const float*)d_in[3];
    const float* Wproj = (const float*)d_in[4];
    const float* qgain = (const float*)d_in[5];
    float* out = (float*)d_out;

    float *q_ptr, *k_ptr;
    cudaGetSymbolAddress((void**)&q_ptr, g_Q);
    cudaGetSymbolAddress((void**)&k_ptr, g_K);
    __half *x16, *wq16h, *wq16l, *wk16h, *wk16l, *wv16h, *wv16l, *wp16h, *wp16l, *y16;
    cudaGetSymbolAddress((void**)&x16, g_x16);
    cudaGetSymbolAddress((void**)&wq16h, g_wq16h); cudaGetSymbolAddress((void**)&wq16l, g_wq16l);
    cudaGetSymbolAddress((void**)&wk16h, g_wk16h); cudaGetSymbolAddress((void**)&wk16l, g_wk16l);
    cudaGetSymbolAddress((void**)&wv16h, g_wv16h); cudaGetSymbolAddress((void**)&wv16l, g_wv16l);
    cudaGetSymbolAddress((void**)&wp16h, g_wp16h); cudaGetSymbolAddress((void**)&wp16l, g_wp16l);
    cudaGetSymbolAddress((void**)&y16, g_y16);
    __nv_bfloat16 *qh2, *ql2, *kh2, *kl2, *vh2, *vl2;
    cudaGetSymbolAddress((void**)&qh2, g_qh2); cudaGetSymbolAddress((void**)&ql2, g_ql2);
    cudaGetSymbolAddress((void**)&kh2, g_kh2); cudaGetSymbolAddress((void**)&kl2, g_kl2);
    cudaGetSymbolAddress((void**)&vh2, g_vh2); cudaGetSymbolAddress((void**)&vl2, g_vl2);

    float* v_out = out + (size_t)NTOK * DIMn;   // v is the second output

    cudaFuncSetAttribute(mma_gemm_qkv, cudaFuncAttributeMaxDynamicSharedMemorySize, GEMM_SMEM);
    cudaFuncSetAttribute(mma_gemm_proj, cudaFuncAttributeMaxDynamicSharedMemorySize, GEMM_SMEM);
    cudaFuncSetAttribute(flash_mma_kernel, cudaFuncAttributeMaxDynamicSharedMemorySize, FLM_SMEM);

    const float qscale = 0.08838834764831845f * 1.4426950408889634f;  // 1/sqrt(D)*log2(e)

    // 1. RoPE tables + fp16 operand splits
    rope_table_kernel<<<(TT * HALF + 255) / 256, 256>>>();
    split_hi_f16<<<(NTOK * DIMn / 4 + 255) / 256, 256>>>(x, x16, NTOK * DIMn / 4);
    split_hilo_f16<<<(DIMn * DIMn / 4 + 255) / 256, 256>>>(Wq, wq16h, wq16l, DIMn * DIMn / 4);
    split_hilo_f16<<<(KVD * DIMn / 4 + 255) / 256, 256>>>(Wk, wk16h, wk16l, KVD * DIMn / 4);
    split_hilo_f16<<<(KVD * DIMn / 4 + 255) / 256, 256>>>(Wv, wv16h, wv16l, KVD * DIMn / 4);
    split_hilo_f16<<<(DIMn * DIMn / 4 + 255) / 256, 256>>>(Wproj, wp16h, wp16l, DIMn * DIMn / 4);

    // 2. fused Q/K/V projections (fp16 2-pass; V -> output tail + bf16 hi/lo)
    mma_gemm_qkv<<<dim3(24, NTOK / 128), 256, GEMM_SMEM>>>(
        x16, wq16h, wq16l, wk16h, wk16l, wv16h, wv16l, q_ptr, k_ptr, v_out, vh2, vl2);

    // 3. RMSNorm + RoPE -> bf16 hi/lo (q: gain + attention scale)
    normrope_split_kernel<<<dim3(NTOK, HH), 128>>>(q_ptr, HH, qgain, 1, qscale, qh2, ql2);
    normrope_split_kernel<<<dim3(NTOK, HKVn), 128>>>(k_ptr, HKVn, nullptr, 0, 1.0f, kh2, kl2);

    // 4. causal GQA flash attention (bf16 3-pass) -> fp16 Y
    flash_mma_kernel<<<dim3(TT / FL_BM, BB * HH), 256, FLM_SMEM>>>(
        qh2, ql2, kh2, kl2, vh2, vl2, y16);

    // 5. output projection (fp16 2-pass)
    mma_gemm_proj<<<dim3(DIMn / 128, NTOK / 128), 256, GEMM_SMEM>>>(y16, wp16h, wp16l, out);
}